// round 1
// baseline (speedup 1.0000x reference)
#include <cuda_runtime.h>

// Problem constants
#define B_  4
#define T_  2048
#define D_  1024
#define H_  16
#define HD_ 64
#define M_  (B_*T_)   // 8192 rows for all GEMMs

// Scratch: Q/K/V in [B*H][T][HD] layout, O in [B][T][D] layout.
__device__ float g_q[(size_t)B_*H_*T_*HD_];
__device__ float g_k[(size_t)B_*H_*T_*HD_];
__device__ float g_v[(size_t)B_*H_*T_*HD_];
__device__ float g_o[(size_t)B_*T_*D_];

// ---------------------------------------------------------------------------
// SGEMM: out = A[M,1024] @ W[1024,1024]^T  (nn.Linear semantics, W is [out,in])
// MODE 0: scatter into [B*H][T][HD] head-major layout (QKV projections)
// MODE 1: write [M,1024] row-major with bias (output projection)
// Tiling: 128x128x8, 256 threads, 8x8 accumulators per thread.
// ---------------------------------------------------------------------------
template<int MODE>
__global__ void __launch_bounds__(256) gemm_kernel(const float* __restrict__ A,
                                                   const float* __restrict__ W,
                                                   float* __restrict__ out,
                                                   const float* __restrict__ bias) {
    constexpr int K  = 1024;
    constexpr int BM = 128, BN = 128, BK = 8;

    __shared__ float As[BK][BM + 4];   // padded: conflict-free transposed stores
    __shared__ float Bs[BK][BN + 4];

    const int tid = threadIdx.x;
    const int bx = blockIdx.x;   // N tile (8 tiles)
    const int by = blockIdx.y;   // M tile (64 tiles)
    const int ty = tid >> 4;     // 0..15
    const int tx = tid & 15;     // 0..15

    const int lrow = tid >> 1;          // 0..127
    const int lcol = (tid & 1) * 4;     // 0 or 4

    const float* Ab = A + (size_t)(by * BM + lrow) * K + lcol;
    const float* Wb = W + (size_t)(bx * BN + lrow) * K + lcol;

    float acc[8][8];
#pragma unroll
    for (int i = 0; i < 8; i++)
#pragma unroll
        for (int j = 0; j < 8; j++) acc[i][j] = 0.f;

    for (int k0 = 0; k0 < K; k0 += BK) {
        float4 a4 = *(const float4*)(Ab + k0);
        float4 b4 = *(const float4*)(Wb + k0);
        As[lcol + 0][lrow] = a4.x;
        As[lcol + 1][lrow] = a4.y;
        As[lcol + 2][lrow] = a4.z;
        As[lcol + 3][lrow] = a4.w;
        Bs[lcol + 0][lrow] = b4.x;
        Bs[lcol + 1][lrow] = b4.y;
        Bs[lcol + 2][lrow] = b4.z;
        Bs[lcol + 3][lrow] = b4.w;
        __syncthreads();

#pragma unroll
        for (int kk = 0; kk < BK; kk++) {
            float4 a0 = *(const float4*)&As[kk][ty * 8];
            float4 a1 = *(const float4*)&As[kk][ty * 8 + 4];
            float4 b0 = *(const float4*)&Bs[kk][tx * 8];
            float4 b1 = *(const float4*)&Bs[kk][tx * 8 + 4];
            float ra[8] = {a0.x, a0.y, a0.z, a0.w, a1.x, a1.y, a1.z, a1.w};
            float rb[8] = {b0.x, b0.y, b0.z, b0.w, b1.x, b1.y, b1.z, b1.w};
#pragma unroll
            for (int i = 0; i < 8; i++)
#pragma unroll
                for (int j = 0; j < 8; j++)
                    acc[i][j] = fmaf(ra[i], rb[j], acc[i][j]);
        }
        __syncthreads();
    }

    if (MODE == 0) {
        // scatter to [B*H][T][HD]
#pragma unroll
        for (int i = 0; i < 8; i++) {
            const int m = by * BM + ty * 8 + i;
            const int b = m >> 11;         // /2048
            const int t = m & 2047;
#pragma unroll
            for (int j = 0; j < 8; j++) {
                const int n = bx * BN + tx * 8 + j;
                const int h = n >> 6;
                const int d = n & 63;
                out[(((size_t)(b * H_ + h)) * T_ + t) * HD_ + d] = acc[i][j];
            }
        }
    } else {
#pragma unroll
        for (int i = 0; i < 8; i++) {
            const int m = by * BM + ty * 8 + i;
#pragma unroll
            for (int j = 0; j < 8; j++) {
                const int n = bx * BN + tx * 8 + j;
                out[(size_t)m * 1024 + n] = acc[i][j] + bias[n];
            }
        }
    }
}

// ---------------------------------------------------------------------------
// Flash attention (causal), fp32. 64-query x 64-key tiles, hd=64.
// 256 threads: 16x16 grid, each thread owns a 4x4 S fragment and 4x4 O fragment.
// Q,K stored transposed in smem ([d][m]) so S-compute is outer-product style:
// 2x LDS.128 per 16 FFMA. P stored transposed ([k][m]) for the same reason in PV.
// ---------------------------------------------------------------------------
#define FL_PAD 68  // row stride (floats), keeps 16B alignment, spreads banks

__global__ void __launch_bounds__(256) flash_kernel() {
    extern __shared__ float sm[];
    float* Qst = sm;                 // [64][FL_PAD]  (d-major: Qst[d][m])
    float* Kst = sm + 64 * FL_PAD;   // [64][FL_PAD]  (d-major: Kst[d][n])
    float* Vs  = sm + 2 * 64 * FL_PAD; // [64][FL_PAD] (k-major natural: Vs[k][dim])
    float* Pst = sm + 3 * 64 * FL_PAD; // [64][FL_PAD] (k-major: Pst[k][m])

    const int tid = threadIdx.x;
    const int ty = tid >> 4;   // 0..15 -> query rows ty*4..ty*4+3
    const int tx = tid & 15;   // 0..15 -> key cols / dims tx*4..tx*4+3
    const int qt = blockIdx.x; // query tile (0..31)
    const int bh = blockIdx.y; // b*H + h  (0..63)

    const float* Qg = g_q + (size_t)bh * T_ * HD_ + (size_t)qt * 64 * HD_;
    const float* Kg = g_k + (size_t)bh * T_ * HD_;
    const float* Vg = g_v + (size_t)bh * T_ * HD_;

    // Load Q tile transposed into smem
    for (int idx = tid; idx < 64 * 16; idx += 256) {
        const int r  = idx >> 4;
        const int c4 = (idx & 15) * 4;
        float4 v = *(const float4*)(Qg + r * 64 + c4);
        Qst[(c4 + 0) * FL_PAD + r] = v.x;
        Qst[(c4 + 1) * FL_PAD + r] = v.y;
        Qst[(c4 + 2) * FL_PAD + r] = v.z;
        Qst[(c4 + 3) * FL_PAD + r] = v.w;
    }

    float o[4][4];
    float mrow[4], lrow[4];
#pragma unroll
    for (int i = 0; i < 4; i++) {
        mrow[i] = -1e30f;
        lrow[i] = 0.f;
#pragma unroll
        for (int j = 0; j < 4; j++) o[i][j] = 0.f;
    }
    const float scale = 0.125f;  // 1/sqrt(64)

    for (int kt = 0; kt <= qt; kt++) {
        __syncthreads();  // prior iter's reads of Kst/Vs/Pst done (also Qst on iter 0 start guard below)
        const float* Kt = Kg + (size_t)kt * 64 * 64;
        const float* Vt = Vg + (size_t)kt * 64 * 64;
        for (int idx = tid; idx < 64 * 16; idx += 256) {
            const int r  = idx >> 4;
            const int c4 = (idx & 15) * 4;
            float4 kv = *(const float4*)(Kt + r * 64 + c4);
            Kst[(c4 + 0) * FL_PAD + r] = kv.x;
            Kst[(c4 + 1) * FL_PAD + r] = kv.y;
            Kst[(c4 + 2) * FL_PAD + r] = kv.z;
            Kst[(c4 + 3) * FL_PAD + r] = kv.w;
            *(float4*)&Vs[r * FL_PAD + c4] = *(const float4*)(Vt + r * 64 + c4);
        }
        __syncthreads();

        // S = Q K^T  (outer product over d)
        float s[4][4];
#pragma unroll
        for (int i = 0; i < 4; i++)
#pragma unroll
            for (int j = 0; j < 4; j++) s[i][j] = 0.f;

#pragma unroll 4
        for (int d = 0; d < 64; d++) {
            float4 q4 = *(const float4*)&Qst[d * FL_PAD + ty * 4];
            float4 k4 = *(const float4*)&Kst[d * FL_PAD + tx * 4];
            float qa[4] = {q4.x, q4.y, q4.z, q4.w};
            float ka[4] = {k4.x, k4.y, k4.z, k4.w};
#pragma unroll
            for (int i = 0; i < 4; i++)
#pragma unroll
                for (int j = 0; j < 4; j++)
                    s[i][j] = fmaf(qa[i], ka[j], s[i][j]);
        }

        // scale + causal mask (only diagonal tile needs masking)
#pragma unroll
        for (int i = 0; i < 4; i++)
#pragma unroll
            for (int j = 0; j < 4; j++) {
                s[i][j] *= scale;
                if (kt == qt && (tx * 4 + j) > (ty * 4 + i)) s[i][j] = -1e30f;
            }

        // online softmax: row max (reduce over 16 tx lanes), exp, row sum
#pragma unroll
        for (int i = 0; i < 4; i++) {
            float rm = s[i][0];
#pragma unroll
            for (int j = 1; j < 4; j++) rm = fmaxf(rm, s[i][j]);
#pragma unroll
            for (int off = 1; off < 16; off <<= 1)
                rm = fmaxf(rm, __shfl_xor_sync(0xffffffffu, rm, off));
            const float mnew = fmaxf(mrow[i], rm);
            const float ex = __expf(mrow[i] - mnew);
            float rs = 0.f;
#pragma unroll
            for (int j = 0; j < 4; j++) {
                s[i][j] = __expf(s[i][j] - mnew);
                rs += s[i][j];
            }
#pragma unroll
            for (int off = 1; off < 16; off <<= 1)
                rs += __shfl_xor_sync(0xffffffffu, rs, off);
            lrow[i] = lrow[i] * ex + rs;
            mrow[i] = mnew;
#pragma unroll
            for (int j = 0; j < 4; j++) o[i][j] *= ex;
        }

        // write P transposed: Pst[k][m]
#pragma unroll
        for (int i = 0; i < 4; i++)
#pragma unroll
            for (int j = 0; j < 4; j++)
                Pst[(tx * 4 + j) * FL_PAD + ty * 4 + i] = s[i][j];
        __syncthreads();

        // O += P @ V  (outer product over k)
#pragma unroll 4
        for (int k = 0; k < 64; k++) {
            float4 p4 = *(const float4*)&Pst[k * FL_PAD + ty * 4];
            float4 v4 = *(const float4*)&Vs[k * FL_PAD + tx * 4];
            float pa[4] = {p4.x, p4.y, p4.z, p4.w};
            float va[4] = {v4.x, v4.y, v4.z, v4.w};
#pragma unroll
            for (int i = 0; i < 4; i++)
#pragma unroll
                for (int j = 0; j < 4; j++)
                    o[i][j] = fmaf(pa[i], va[j], o[i][j]);
        }
    }

    // epilogue: normalize and write to [B][T][D] layout (head-interleaved)
    const int b = bh >> 4;
    const int h = bh & 15;
#pragma unroll
    for (int i = 0; i < 4; i++) {
        const float inv = 1.f / lrow[i];
        const int t = qt * 64 + ty * 4 + i;
        float4 r;
        r.x = o[i][0] * inv;
        r.y = o[i][1] * inv;
        r.z = o[i][2] * inv;
        r.w = o[i][3] * inv;
        *(float4*)&g_o[((size_t)(b * T_ + t)) * D_ + h * HD_ + tx * 4] = r;
    }
}

// ---------------------------------------------------------------------------
// Launch
// ---------------------------------------------------------------------------
extern "C" void kernel_launch(void* const* d_in, const int* in_sizes, int n_in,
                              void* d_out, int out_size) {
    const float* x  = (const float*)d_in[0];
    const float* Wk = (const float*)d_in[1];
    const float* Wq = (const float*)d_in[2];
    const float* Wv = (const float*)d_in[3];
    const float* Wp = (const float*)d_in[4];
    const float* bp = (const float*)d_in[5];
    float* out = (float*)d_out;

    float *qp, *kp, *vp, *op;
    cudaGetSymbolAddress((void**)&qp, g_q);
    cudaGetSymbolAddress((void**)&kp, g_k);
    cudaGetSymbolAddress((void**)&vp, g_v);
    cudaGetSymbolAddress((void**)&op, g_o);

    dim3 gg(D_ / 128, M_ / 128);  // (8, 64)
    gemm_kernel<0><<<gg, 256>>>(x, Wk, kp, nullptr);
    gemm_kernel<0><<<gg, 256>>>(x, Wq, qp, nullptr);
    gemm_kernel<0><<<gg, 256>>>(x, Wv, vp, nullptr);

    const int smem = 4 * 64 * FL_PAD * sizeof(float);  // 69632 B
    cudaFuncSetAttribute(flash_kernel, cudaFuncAttributeMaxDynamicSharedMemorySize, smem);
    flash_kernel<<<dim3(T_ / 64, B_ * H_), 256, smem>>>();

    gemm_kernel<1><<<gg, 256>>>(op, Wp, out, bp);
}

// round 3
// speedup vs baseline: 1.7844x; 1.7844x over previous
#include <cuda_runtime.h>
#include <cstdint>

// Problem constants
#define B_  4
#define T_  2048
#define D_  1024
#define H_  16
#define HD_ 64
#define M_  (B_*T_)   // 8192

// Scratch buffers
__device__ float g_q[(size_t)B_*H_*T_*HD_];
__device__ float g_k[(size_t)B_*H_*T_*HD_];
__device__ float g_v[(size_t)B_*H_*T_*HD_];
__device__ float g_o[(size_t)B_*T_*D_];
__device__ float g_xr[(size_t)B_*T_*D_];   // tf32-rounded activations
__device__ float g_wr[(size_t)D_*D_];      // tf32-rounded weight (reused)

// ---------------------------------------------------------------------------
// helpers
// ---------------------------------------------------------------------------
__device__ __forceinline__ uint32_t smem_u32(const void* p) {
    uint32_t a;
    asm("{ .reg .u64 t; cvta.to.shared.u64 t, %1; cvt.u32.u64 %0, t; }"
        : "=r"(a) : "l"(p));
    return a;
}

__device__ __forceinline__ void cp_async16(uint32_t dst, const void* src) {
    asm volatile("cp.async.cg.shared.global [%0], [%1], 16;" :: "r"(dst), "l"(src));
}

__device__ __forceinline__ void mma_tf32(float* c, const uint32_t* a, const uint32_t* b) {
    asm volatile(
        "mma.sync.aligned.m16n8k8.row.col.f32.tf32.tf32.f32 "
        "{%0,%1,%2,%3}, {%4,%5,%6,%7}, {%8,%9}, {%0,%1,%2,%3};"
        : "+f"(c[0]), "+f"(c[1]), "+f"(c[2]), "+f"(c[3])
        : "r"(a[0]), "r"(a[1]), "r"(a[2]), "r"(a[3]), "r"(b[0]), "r"(b[1]));
}

// ---------------------------------------------------------------------------
// tf32 pre-rounding: y[i] = round_rna_tf32(x[i]), vectorized x4
// ---------------------------------------------------------------------------
__global__ void __launch_bounds__(256) round_tf32(const float* __restrict__ x,
                                                  float* __restrict__ y) {
    const size_t i = ((size_t)blockIdx.x * 256 + threadIdx.x) * 4;
    float4 v = *(const float4*)(x + i);
    uint32_t a, b, c, d;
    asm("cvt.rna.tf32.f32 %0, %1;" : "=r"(a) : "f"(v.x));
    asm("cvt.rna.tf32.f32 %0, %1;" : "=r"(b) : "f"(v.y));
    asm("cvt.rna.tf32.f32 %0, %1;" : "=r"(c) : "f"(v.z));
    asm("cvt.rna.tf32.f32 %0, %1;" : "=r"(d) : "f"(v.w));
    float4 o;
    o.x = __uint_as_float(a); o.y = __uint_as_float(b);
    o.z = __uint_as_float(c); o.w = __uint_as_float(d);
    *(float4*)(y + i) = o;
}

// ---------------------------------------------------------------------------
// mma.sync tf32 GEMM: out = A[8192,1024] @ W[1024,1024]^T
// CTA 128x128, BK=32, double-buffered cp.async, 8 warps (2x4), warp tile 64x32.
// SMEM rows padded to 36 floats -> fragment gather is bank-conflict-free.
// MODE 0: scatter to [B*H][T][HD];  MODE 1: row-major + bias
// ---------------------------------------------------------------------------
#define SROW 36                 // floats per smem row (32 data + 4 pad)
#define TILE_F (128 * SROW)     // floats per A or B tile = 4608
#define BUF_F  (2 * TILE_F)     // floats per stage (A+B) = 9216

template<int MODE>
__global__ void __launch_bounds__(256) gemm_mma(const float* __restrict__ A,
                                                const float* __restrict__ W,
                                                float* __restrict__ out,
                                                const float* __restrict__ bias) {
    extern __shared__ float sm[];
    const int tid  = threadIdx.x;
    const int lane = tid & 31;
    const int wid  = tid >> 5;
    const int wm   = wid >> 2;       // 0..1
    const int wn   = wid & 3;        // 0..3
    const int bx = blockIdx.x;       // N tile (8)
    const int by = blockIdx.y;       // M tile (64)

    float c[4][4][4];
#pragma unroll
    for (int i = 0; i < 4; i++)
#pragma unroll
        for (int j = 0; j < 4; j++)
#pragma unroll
            for (int k = 0; k < 4; k++) c[i][j][k] = 0.f;

    // gmem load geometry: each thread does 4x16B for A + 4x16B for B per tile
    const int lr = tid >> 3;     // 0..31 (row group)
    const int ls = tid & 7;      // 16B segment in 128B row
    const float* Ag = A + (size_t)(by * 128 + lr) * 1024 + ls * 4;
    const float* Wg = W + (size_t)(bx * 128 + lr) * 1024 + ls * 4;

    const uint32_t sbase = smem_u32(sm);
    const uint32_t ldst  = sbase + lr * (SROW * 4) + ls * 16;

    auto load_tile = [&](int kt, int s) {
        const uint32_t aB = ldst + (uint32_t)s * (BUF_F * 4);
        const uint32_t bB = aB + TILE_F * 4;
        const float* Ak = Ag + kt * 32;
        const float* Wk = Wg + kt * 32;
#pragma unroll
        for (int i = 0; i < 4; i++) {
            cp_async16(aB + i * 32 * (SROW * 4), Ak + (size_t)i * 32 * 1024);
            cp_async16(bB + i * 32 * (SROW * 4), Wk + (size_t)i * 32 * 1024);
        }
        asm volatile("cp.async.commit_group;" ::: "memory");
    };

    load_tile(0, 0);

    const int frow = lane >> 2;      // 0..7
    const int fcol = lane & 3;       // 0..3

    for (int kt = 0; kt < 32; kt++) {
        const int s = kt & 1;
        if (kt < 31) {
            load_tile(kt + 1, s ^ 1);
            asm volatile("cp.async.wait_group 1;" ::: "memory");
        } else {
            asm volatile("cp.async.wait_group 0;" ::: "memory");
        }
        __syncthreads();

        const uint32_t* As = (const uint32_t*)(sm + s * BUF_F) +
                             (wm * 64 + frow) * SROW;
        const uint32_t* Bs = (const uint32_t*)(sm + s * BUF_F + TILE_F) +
                             (wn * 32 + frow) * SROW;
#pragma unroll
        for (int ks = 0; ks < 4; ks++) {
            const int k0 = ks * 8 + fcol;
            uint32_t a[4][4], b[4][2];
#pragma unroll
            for (int mm = 0; mm < 4; mm++) {
                a[mm][0] = As[mm * 16 * SROW + k0];
                a[mm][1] = As[(mm * 16 + 8) * SROW + k0];
                a[mm][2] = As[mm * 16 * SROW + k0 + 4];
                a[mm][3] = As[(mm * 16 + 8) * SROW + k0 + 4];
            }
#pragma unroll
            for (int nn = 0; nn < 4; nn++) {
                b[nn][0] = Bs[nn * 8 * SROW + k0];
                b[nn][1] = Bs[nn * 8 * SROW + k0 + 4];
            }
#pragma unroll
            for (int mm = 0; mm < 4; mm++)
#pragma unroll
                for (int nn = 0; nn < 4; nn++)
                    mma_tf32(c[mm][nn], a[mm], b[nn]);
        }
        __syncthreads();
    }

    // epilogue: C fragment -> gmem (float2 stores)
    const int rbase = by * 128 + wm * 64 + frow;
    const int cbase = bx * 128 + wn * 32 + fcol * 2;
#pragma unroll
    for (int mm = 0; mm < 4; mm++) {
        const int r0 = rbase + mm * 16;
#pragma unroll
        for (int nn = 0; nn < 4; nn++) {
            const int cc = cbase + nn * 8;
            if (MODE == 0) {
                const int h = cc >> 6, d = cc & 63;
                const int b = r0 >> 11, t = r0 & 2047;
                float* dst = g_q; // placeholder, replaced below
                dst = out + (((size_t)(b * H_ + h)) * T_ + t) * HD_ + d;
                *(float2*)dst = make_float2(c[mm][nn][0], c[mm][nn][1]);
                *(float2*)(dst + 8 * HD_) = make_float2(c[mm][nn][2], c[mm][nn][3]);
            } else {
                float2 bb = *(const float2*)(bias + cc);
                float* dst = out + (size_t)r0 * 1024 + cc;
                *(float2*)dst = make_float2(c[mm][nn][0] + bb.x, c[mm][nn][1] + bb.y);
                *(float2*)(dst + 8 * 1024) =
                    make_float2(c[mm][nn][2] + bb.x, c[mm][nn][3] + bb.y);
            }
        }
    }
}

// ---------------------------------------------------------------------------
// Flash attention (causal), fp32 — unchanged (known good).
// ---------------------------------------------------------------------------
#define FL_PAD 68

__global__ void __launch_bounds__(256) flash_kernel() {
    extern __shared__ float sm[];
    float* Qst = sm;
    float* Kst = sm + 64 * FL_PAD;
    float* Vs  = sm + 2 * 64 * FL_PAD;
    float* Pst = sm + 3 * 64 * FL_PAD;

    const int tid = threadIdx.x;
    const int ty = tid >> 4;
    const int tx = tid & 15;
    const int qt = blockIdx.x;
    const int bh = blockIdx.y;

    const float* Qg = g_q + (size_t)bh * T_ * HD_ + (size_t)qt * 64 * HD_;
    const float* Kg = g_k + (size_t)bh * T_ * HD_;
    const float* Vg = g_v + (size_t)bh * T_ * HD_;

    for (int idx = tid; idx < 64 * 16; idx += 256) {
        const int r  = idx >> 4;
        const int c4 = (idx & 15) * 4;
        float4 v = *(const float4*)(Qg + r * 64 + c4);
        Qst[(c4 + 0) * FL_PAD + r] = v.x;
        Qst[(c4 + 1) * FL_PAD + r] = v.y;
        Qst[(c4 + 2) * FL_PAD + r] = v.z;
        Qst[(c4 + 3) * FL_PAD + r] = v.w;
    }

    float o[4][4];
    float mrow[4], lrow[4];
#pragma unroll
    for (int i = 0; i < 4; i++) {
        mrow[i] = -1e30f;
        lrow[i] = 0.f;
#pragma unroll
        for (int j = 0; j < 4; j++) o[i][j] = 0.f;
    }
    const float scale = 0.125f;

    for (int kt = 0; kt <= qt; kt++) {
        __syncthreads();
        const float* Kt = Kg + (size_t)kt * 64 * 64;
        const float* Vt = Vg + (size_t)kt * 64 * 64;
        for (int idx = tid; idx < 64 * 16; idx += 256) {
            const int r  = idx >> 4;
            const int c4 = (idx & 15) * 4;
            float4 kv = *(const float4*)(Kt + r * 64 + c4);
            Kst[(c4 + 0) * FL_PAD + r] = kv.x;
            Kst[(c4 + 1) * FL_PAD + r] = kv.y;
            Kst[(c4 + 2) * FL_PAD + r] = kv.z;
            Kst[(c4 + 3) * FL_PAD + r] = kv.w;
            *(float4*)&Vs[r * FL_PAD + c4] = *(const float4*)(Vt + r * 64 + c4);
        }
        __syncthreads();

        float s[4][4];
#pragma unroll
        for (int i = 0; i < 4; i++)
#pragma unroll
            for (int j = 0; j < 4; j++) s[i][j] = 0.f;

#pragma unroll 4
        for (int d = 0; d < 64; d++) {
            float4 q4 = *(const float4*)&Qst[d * FL_PAD + ty * 4];
            float4 k4 = *(const float4*)&Kst[d * FL_PAD + tx * 4];
            float qa[4] = {q4.x, q4.y, q4.z, q4.w};
            float ka[4] = {k4.x, k4.y, k4.z, k4.w};
#pragma unroll
            for (int i = 0; i < 4; i++)
#pragma unroll
                for (int j = 0; j < 4; j++)
                    s[i][j] = fmaf(qa[i], ka[j], s[i][j]);
        }

#pragma unroll
        for (int i = 0; i < 4; i++)
#pragma unroll
            for (int j = 0; j < 4; j++) {
                s[i][j] *= scale;
                if (kt == qt && (tx * 4 + j) > (ty * 4 + i)) s[i][j] = -1e30f;
            }

#pragma unroll
        for (int i = 0; i < 4; i++) {
            float rm = s[i][0];
#pragma unroll
            for (int j = 1; j < 4; j++) rm = fmaxf(rm, s[i][j]);
#pragma unroll
            for (int off = 1; off < 16; off <<= 1)
                rm = fmaxf(rm, __shfl_xor_sync(0xffffffffu, rm, off));
            const float mnew = fmaxf(mrow[i], rm);
            const float ex = __expf(mrow[i] - mnew);
            float rs = 0.f;
#pragma unroll
            for (int j = 0; j < 4; j++) {
                s[i][j] = __expf(s[i][j] - mnew);
                rs += s[i][j];
            }
#pragma unroll
            for (int off = 1; off < 16; off <<= 1)
                rs += __shfl_xor_sync(0xffffffffu, rs, off);
            lrow[i] = lrow[i] * ex + rs;
            mrow[i] = mnew;
#pragma unroll
            for (int j = 0; j < 4; j++) o[i][j] *= ex;
        }

#pragma unroll
        for (int i = 0; i < 4; i++)
#pragma unroll
            for (int j = 0; j < 4; j++)
                Pst[(tx * 4 + j) * FL_PAD + ty * 4 + i] = s[i][j];
        __syncthreads();

#pragma unroll 4
        for (int k = 0; k < 64; k++) {
            float4 p4 = *(const float4*)&Pst[k * FL_PAD + ty * 4];
            float4 v4 = *(const float4*)&Vs[k * FL_PAD + tx * 4];
            float pa[4] = {p4.x, p4.y, p4.z, p4.w};
            float va[4] = {v4.x, v4.y, v4.z, v4.w};
#pragma unroll
            for (int i = 0; i < 4; i++)
#pragma unroll
                for (int j = 0; j < 4; j++)
                    o[i][j] = fmaf(pa[i], va[j], o[i][j]);
        }
    }

    const int b = bh >> 4;
    const int h = bh & 15;
#pragma unroll
    for (int i = 0; i < 4; i++) {
        const float inv = 1.f / lrow[i];
        const int t = qt * 64 + ty * 4 + i;
        float4 r;
        r.x = o[i][0] * inv;
        r.y = o[i][1] * inv;
        r.z = o[i][2] * inv;
        r.w = o[i][3] * inv;
        *(float4*)&g_o[((size_t)(b * T_ + t)) * D_ + h * HD_ + tx * 4] = r;
    }
}

// ---------------------------------------------------------------------------
// Launch
// ---------------------------------------------------------------------------
extern "C" void kernel_launch(void* const* d_in, const int* in_sizes, int n_in,
                              void* d_out, int out_size) {
    const float* x  = (const float*)d_in[0];
    const float* Wk = (const float*)d_in[1];
    const float* Wq = (const float*)d_in[2];
    const float* Wv = (const float*)d_in[3];
    const float* Wp = (const float*)d_in[4];
    const float* bp = (const float*)d_in[5];
    float* out = (float*)d_out;

    float *qp, *kp, *vp, *op, *xr, *wr;
    cudaGetSymbolAddress((void**)&qp, g_q);
    cudaGetSymbolAddress((void**)&kp, g_k);
    cudaGetSymbolAddress((void**)&vp, g_v);
    cudaGetSymbolAddress((void**)&op, g_o);
    cudaGetSymbolAddress((void**)&xr, g_xr);
    cudaGetSymbolAddress((void**)&wr, g_wr);

    const int gemm_smem = 2 * BUF_F * sizeof(float);  // 73728
    cudaFuncSetAttribute(gemm_mma<0>, cudaFuncAttributeMaxDynamicSharedMemorySize, gemm_smem);
    cudaFuncSetAttribute(gemm_mma<1>, cudaFuncAttributeMaxDynamicSharedMemorySize, gemm_smem);

    const int NX = B_ * T_ * D_;     // 8388608
    const int NW = D_ * D_;          // 1048576

    dim3 gg(D_ / 128, M_ / 128);     // (8, 64)

    // QKV projections (tf32 mma.sync)
    round_tf32<<<NX / 1024, 256>>>(x, xr);
    round_tf32<<<NW / 1024, 256>>>(Wk, wr);
    gemm_mma<0><<<gg, 256, gemm_smem>>>(xr, wr, kp, nullptr);
    round_tf32<<<NW / 1024, 256>>>(Wq, wr);
    gemm_mma<0><<<gg, 256, gemm_smem>>>(xr, wr, qp, nullptr);
    round_tf32<<<NW / 1024, 256>>>(Wv, wr);
    gemm_mma<0><<<gg, 256, gemm_smem>>>(xr, wr, vp, nullptr);

    // attention (fp32)
    const int fl_smem = 4 * 64 * FL_PAD * sizeof(float);
    cudaFuncSetAttribute(flash_kernel, cudaFuncAttributeMaxDynamicSharedMemorySize, fl_smem);
    flash_kernel<<<dim3(T_ / 64, B_ * H_), 256, fl_smem>>>();

    // output projection (tf32 mma.sync)
    round_tf32<<<NW / 1024, 256>>>(Wp, wr);
    round_tf32<<<NX / 1024, 256>>>(op, xr);
    gemm_mma<1><<<gg, 256, gemm_smem>>>(xr, wr, out, bp);
}

// round 4
// speedup vs baseline: 3.2745x; 1.8350x over previous
#include <cuda_runtime.h>
#include <cstdint>

// Problem constants
#define B_  4
#define T_  2048
#define D_  1024
#define H_  16
#define HD_ 64
#define M_  (B_*T_)   // 8192

// Scratch buffers
__device__ float g_q[(size_t)B_*H_*T_*HD_];
__device__ float g_k[(size_t)B_*H_*T_*HD_];
__device__ float g_v[(size_t)B_*H_*T_*HD_];
__device__ float g_o[(size_t)B_*T_*D_];
__device__ float g_xr[(size_t)B_*T_*D_];   // tf32-rounded activations
__device__ float g_wr[(size_t)D_*D_];      // tf32-rounded weight (reused)

// ---------------------------------------------------------------------------
// helpers
// ---------------------------------------------------------------------------
__device__ __forceinline__ uint32_t smem_u32(const void* p) {
    uint32_t a;
    asm("{ .reg .u64 t; cvta.to.shared.u64 t, %1; cvt.u32.u64 %0, t; }"
        : "=r"(a) : "l"(p));
    return a;
}

__device__ __forceinline__ void cp_async16(uint32_t dst, const void* src) {
    asm volatile("cp.async.cg.shared.global [%0], [%1], 16;" :: "r"(dst), "l"(src));
}

__device__ __forceinline__ void mma_tf32(float* c, const uint32_t* a, const uint32_t* b) {
    asm volatile(
        "mma.sync.aligned.m16n8k8.row.col.f32.tf32.tf32.f32 "
        "{%0,%1,%2,%3}, {%4,%5,%6,%7}, {%8,%9}, {%0,%1,%2,%3};"
        : "+f"(c[0]), "+f"(c[1]), "+f"(c[2]), "+f"(c[3])
        : "r"(a[0]), "r"(a[1]), "r"(a[2]), "r"(a[3]), "r"(b[0]), "r"(b[1]));
}

__device__ __forceinline__ void mma_tf32_b(float* c, const uint32_t* a,
                                           uint32_t b0, uint32_t b1) {
    asm volatile(
        "mma.sync.aligned.m16n8k8.row.col.f32.tf32.tf32.f32 "
        "{%0,%1,%2,%3}, {%4,%5,%6,%7}, {%8,%9}, {%0,%1,%2,%3};"
        : "+f"(c[0]), "+f"(c[1]), "+f"(c[2]), "+f"(c[3])
        : "r"(a[0]), "r"(a[1]), "r"(a[2]), "r"(a[3]), "r"(b0), "r"(b1));
}

__device__ __forceinline__ float rna_tf32(float x) {
    uint32_t u;
    asm("cvt.rna.tf32.f32 %0, %1;" : "=r"(u) : "f"(x));
    return __uint_as_float(u);
}

// ---------------------------------------------------------------------------
// tf32 pre-rounding: y[i] = round_rna_tf32(x[i]), vectorized x4
// ---------------------------------------------------------------------------
__global__ void __launch_bounds__(256) round_tf32(const float* __restrict__ x,
                                                  float* __restrict__ y) {
    const size_t i = ((size_t)blockIdx.x * 256 + threadIdx.x) * 4;
    float4 v = *(const float4*)(x + i);
    float4 o;
    o.x = rna_tf32(v.x); o.y = rna_tf32(v.y);
    o.z = rna_tf32(v.z); o.w = rna_tf32(v.w);
    *(float4*)(y + i) = o;
}

// ---------------------------------------------------------------------------
// mma.sync tf32 GEMM: out = A[8192,1024] @ W[1024,1024]^T
// CTA 128x128, BK=32, double-buffered cp.async, 8 warps (2x4), warp tile 64x32.
// MODE 0: scatter to [B*H][T][HD], values rounded to tf32 (consumed by attn MMA)
// MODE 1: row-major + bias (final output, full fp32)
// ---------------------------------------------------------------------------
#define SROW 36
#define TILE_F (128 * SROW)
#define BUF_F  (2 * TILE_F)

template<int MODE>
__global__ void __launch_bounds__(256) gemm_mma(const float* __restrict__ A,
                                                const float* __restrict__ W,
                                                float* __restrict__ out,
                                                const float* __restrict__ bias) {
    extern __shared__ float sm[];
    const int tid  = threadIdx.x;
    const int lane = tid & 31;
    const int wid  = tid >> 5;
    const int wm   = wid >> 2;
    const int wn   = wid & 3;
    const int bx = blockIdx.x;
    const int by = blockIdx.y;

    float c[4][4][4];
#pragma unroll
    for (int i = 0; i < 4; i++)
#pragma unroll
        for (int j = 0; j < 4; j++)
#pragma unroll
            for (int k = 0; k < 4; k++) c[i][j][k] = 0.f;

    const int lr = tid >> 3;
    const int ls = tid & 7;
    const float* Ag = A + (size_t)(by * 128 + lr) * 1024 + ls * 4;
    const float* Wg = W + (size_t)(bx * 128 + lr) * 1024 + ls * 4;

    const uint32_t sbase = smem_u32(sm);
    const uint32_t ldst  = sbase + lr * (SROW * 4) + ls * 16;

    auto load_tile = [&](int kt, int s) {
        const uint32_t aB = ldst + (uint32_t)s * (BUF_F * 4);
        const uint32_t bB = aB + TILE_F * 4;
        const float* Ak = Ag + kt * 32;
        const float* Wk = Wg + kt * 32;
#pragma unroll
        for (int i = 0; i < 4; i++) {
            cp_async16(aB + i * 32 * (SROW * 4), Ak + (size_t)i * 32 * 1024);
            cp_async16(bB + i * 32 * (SROW * 4), Wk + (size_t)i * 32 * 1024);
        }
        asm volatile("cp.async.commit_group;" ::: "memory");
    };

    load_tile(0, 0);

    const int frow = lane >> 2;
    const int fcol = lane & 3;

    for (int kt = 0; kt < 32; kt++) {
        const int s = kt & 1;
        if (kt < 31) {
            load_tile(kt + 1, s ^ 1);
            asm volatile("cp.async.wait_group 1;" ::: "memory");
        } else {
            asm volatile("cp.async.wait_group 0;" ::: "memory");
        }
        __syncthreads();

        const uint32_t* As = (const uint32_t*)(sm + s * BUF_F) +
                             (wm * 64 + frow) * SROW;
        const uint32_t* Bs = (const uint32_t*)(sm + s * BUF_F + TILE_F) +
                             (wn * 32 + frow) * SROW;
#pragma unroll
        for (int ks = 0; ks < 4; ks++) {
            const int k0 = ks * 8 + fcol;
            uint32_t a[4][4], b[4][2];
#pragma unroll
            for (int mm = 0; mm < 4; mm++) {
                a[mm][0] = As[mm * 16 * SROW + k0];
                a[mm][1] = As[(mm * 16 + 8) * SROW + k0];
                a[mm][2] = As[mm * 16 * SROW + k0 + 4];
                a[mm][3] = As[(mm * 16 + 8) * SROW + k0 + 4];
            }
#pragma unroll
            for (int nn = 0; nn < 4; nn++) {
                b[nn][0] = Bs[nn * 8 * SROW + k0];
                b[nn][1] = Bs[nn * 8 * SROW + k0 + 4];
            }
#pragma unroll
            for (int mm = 0; mm < 4; mm++)
#pragma unroll
                for (int nn = 0; nn < 4; nn++)
                    mma_tf32(c[mm][nn], a[mm], b[nn]);
        }
        __syncthreads();
    }

    const int rbase = by * 128 + wm * 64 + frow;
    const int cbase = bx * 128 + wn * 32 + fcol * 2;
#pragma unroll
    for (int mm = 0; mm < 4; mm++) {
        const int r0 = rbase + mm * 16;
#pragma unroll
        for (int nn = 0; nn < 4; nn++) {
            const int cc = cbase + nn * 8;
            if (MODE == 0) {
                const int h = cc >> 6, d = cc & 63;
                const int b = r0 >> 11, t = r0 & 2047;
                float* dst = out + (((size_t)(b * H_ + h)) * T_ + t) * HD_ + d;
                *(float2*)dst =
                    make_float2(rna_tf32(c[mm][nn][0]), rna_tf32(c[mm][nn][1]));
                *(float2*)(dst + 8 * HD_) =
                    make_float2(rna_tf32(c[mm][nn][2]), rna_tf32(c[mm][nn][3]));
            } else {
                float2 bb = *(const float2*)(bias + cc);
                float* dst = out + (size_t)r0 * 1024 + cc;
                *(float2*)dst = make_float2(c[mm][nn][0] + bb.x, c[mm][nn][1] + bb.y);
                *(float2*)(dst + 8 * 1024) =
                    make_float2(c[mm][nn][2] + bb.x, c[mm][nn][3] + bb.y);
            }
        }
    }
}

// ---------------------------------------------------------------------------
// Tensor-core flash attention (causal), tf32 mma.sync.
// CTA: 128 queries x hd 64, 8 warps (16 query rows each). K-tile = 64 keys.
// smem: K double-buffered (cp.async), Vt transposed (LDG->STS prefetch), P.
// ---------------------------------------------------------------------------
#define PADK 68
#define KS_F (64 * PADK)

__global__ void __launch_bounds__(256) flash_mma() {
    extern __shared__ float sm[];
    float* Ks = sm;                       // [2][64][PADK] key-major
    float* Vt = sm + 2 * KS_F;            // [64][PADK]  (d, key)
    float* Ps = sm + 3 * KS_F;            // [128][PADK] (staging Q, then P)

    const int tid = threadIdx.x, lane = tid & 31, wid = tid >> 5;
    const int g = lane >> 2, q = lane & 3;
    const int qt = blockIdx.x, bh = blockIdx.y;
    const int w16 = wid * 16;

    const float* Qg = g_q + (size_t)bh * T_ * HD_ + (size_t)qt * 128 * HD_;
    const float* Kg = g_k + (size_t)bh * T_ * HD_;
    const float* Vg = g_v + (size_t)bh * T_ * HD_;

    const uint32_t sb  = smem_u32(sm);
    const uint32_t VtB = sb + 2 * KS_F * 4;
    const uint32_t PsB = VtB + KS_F * 4;

    // ---- prologue: stage Q into Ps, K(0) via cp.async, V(0) via LDG ----
    {
        const int row = tid >> 1, segb = (tid & 1) * 8;
#pragma unroll
        for (int i = 0; i < 8; i++)
            cp_async16(PsB + (row * PADK + (segb + i) * 4) * 4,
                       Qg + row * 64 + (segb + i) * 4);
    }
#pragma unroll
    for (int i = 0; i < 4; i++) {
        const int idx = tid + i * 256;
        cp_async16(sb + ((idx >> 4) * PADK + (idx & 15) * 4) * 4,
                   Kg + (idx >> 4) * 64 + (idx & 15) * 4);
    }
    asm volatile("cp.async.commit_group;" ::: "memory");

    const int vr = tid & 63, vqr = tid >> 6;
    float4 vreg[4];
#pragma unroll
    for (int i = 0; i < 4; i++)
        vreg[i] = *(const float4*)(Vg + vr * 64 + vqr * 16 + i * 4);

    asm volatile("cp.async.wait_group 0;" ::: "memory");
    __syncthreads();

    // Q fragments in registers, pre-scaled by 1/sqrt(hd) (exact on tf32)
    uint32_t qf[8][4];
#pragma unroll
    for (int ks = 0; ks < 8; ks++) {
        qf[ks][0] = __float_as_uint(Ps[(w16 + g) * PADK + ks * 8 + q] * 0.125f);
        qf[ks][1] = __float_as_uint(Ps[(w16 + g + 8) * PADK + ks * 8 + q] * 0.125f);
        qf[ks][2] = __float_as_uint(Ps[(w16 + g) * PADK + ks * 8 + q + 4] * 0.125f);
        qf[ks][3] = __float_as_uint(Ps[(w16 + g + 8) * PADK + ks * 8 + q + 4] * 0.125f);
    }
    __syncthreads();   // Q staging reads done before Ps is reused for P

    // V(0) -> Vt transposed
#pragma unroll
    for (int i = 0; i < 4; i++) {
        Vt[(vqr * 16 + i * 4 + 0) * PADK + vr] = vreg[i].x;
        Vt[(vqr * 16 + i * 4 + 1) * PADK + vr] = vreg[i].y;
        Vt[(vqr * 16 + i * 4 + 2) * PADK + vr] = vreg[i].z;
        Vt[(vqr * 16 + i * 4 + 3) * PADK + vr] = vreg[i].w;
    }
    __syncthreads();

    float o_[8][4];
#pragma unroll
    for (int j = 0; j < 8; j++)
#pragma unroll
        for (int k = 0; k < 4; k++) o_[j][k] = 0.f;
    float m0 = -1e30f, m1 = -1e30f, l0 = 0.f, l1 = 0.f;

    const int nkt = 2 * qt + 2;
    for (int kt = 0; kt < nkt; kt++) {
        const int s = kt & 1;

        // prefetch next K (cp.async) and V (regs)
        if (kt + 1 < nkt) {
            const float* Kn = Kg + (size_t)(kt + 1) * 64 * 64;
#pragma unroll
            for (int i = 0; i < 4; i++) {
                const int idx = tid + i * 256;
                cp_async16(sb + ((s ^ 1) * KS_F + (idx >> 4) * PADK + (idx & 15) * 4) * 4,
                           Kn + (idx >> 4) * 64 + (idx & 15) * 4);
            }
            asm volatile("cp.async.commit_group;" ::: "memory");
            const float* Vn = Vg + (size_t)(kt + 1) * 64 * 64;
#pragma unroll
            for (int i = 0; i < 4; i++)
                vreg[i] = *(const float4*)(Vn + vr * 64 + vqr * 16 + i * 4);
        }

        // ---- S = Q K^T ----
        float s_[8][4];
#pragma unroll
        for (int j = 0; j < 8; j++)
#pragma unroll
            for (int k = 0; k < 4; k++) s_[j][k] = 0.f;

        const float* Kb = Ks + s * KS_F;
#pragma unroll
        for (int ks = 0; ks < 8; ks++) {
#pragma unroll
            for (int j = 0; j < 8; j++) {
                const uint32_t b0 = __float_as_uint(Kb[(j * 8 + g) * PADK + ks * 8 + q]);
                const uint32_t b1 = __float_as_uint(Kb[(j * 8 + g) * PADK + ks * 8 + q + 4]);
                mma_tf32_b(s_[j], qf[ks], b0, b1);
            }
        }

        // ---- causal mask (last two tiles only) ----
        if (kt >= 2 * qt) {
            const int kb = kt * 64;
            const int r0 = qt * 128 + w16 + g, r1 = r0 + 8;
#pragma unroll
            for (int j = 0; j < 8; j++) {
                const int k0 = kb + j * 8 + 2 * q;
                if (k0 > r0)     s_[j][0] = -1e30f;
                if (k0 + 1 > r0) s_[j][1] = -1e30f;
                if (k0 > r1)     s_[j][2] = -1e30f;
                if (k0 + 1 > r1) s_[j][3] = -1e30f;
            }
        }

        // ---- online softmax ----
        float mx0 = -1e30f, mx1 = -1e30f;
#pragma unroll
        for (int j = 0; j < 8; j++) {
            mx0 = fmaxf(mx0, fmaxf(s_[j][0], s_[j][1]));
            mx1 = fmaxf(mx1, fmaxf(s_[j][2], s_[j][3]));
        }
        mx0 = fmaxf(mx0, __shfl_xor_sync(0xffffffffu, mx0, 1));
        mx0 = fmaxf(mx0, __shfl_xor_sync(0xffffffffu, mx0, 2));
        mx1 = fmaxf(mx1, __shfl_xor_sync(0xffffffffu, mx1, 1));
        mx1 = fmaxf(mx1, __shfl_xor_sync(0xffffffffu, mx1, 2));

        const float mn0 = fmaxf(m0, mx0), mn1 = fmaxf(m1, mx1);
        const float ex0 = __expf(m0 - mn0), ex1 = __expf(m1 - mn1);
        float rs0 = 0.f, rs1 = 0.f;
#pragma unroll
        for (int j = 0; j < 8; j++) {
            s_[j][0] = rna_tf32(__expf(s_[j][0] - mn0));
            s_[j][1] = rna_tf32(__expf(s_[j][1] - mn0));
            s_[j][2] = rna_tf32(__expf(s_[j][2] - mn1));
            s_[j][3] = rna_tf32(__expf(s_[j][3] - mn1));
            rs0 += s_[j][0] + s_[j][1];
            rs1 += s_[j][2] + s_[j][3];
        }
        rs0 += __shfl_xor_sync(0xffffffffu, rs0, 1);
        rs0 += __shfl_xor_sync(0xffffffffu, rs0, 2);
        rs1 += __shfl_xor_sync(0xffffffffu, rs1, 1);
        rs1 += __shfl_xor_sync(0xffffffffu, rs1, 2);
        l0 = l0 * ex0 + rs0;  m0 = mn0;
        l1 = l1 * ex1 + rs1;  m1 = mn1;
#pragma unroll
        for (int j = 0; j < 8; j++) {
            o_[j][0] *= ex0; o_[j][1] *= ex0;
            o_[j][2] *= ex1; o_[j][3] *= ex1;
        }

        // ---- P -> smem (own rows only; cross-lane within warp) ----
#pragma unroll
        for (int j = 0; j < 8; j++) {
            *(float2*)&Ps[(w16 + g) * PADK + j * 8 + 2 * q] =
                make_float2(s_[j][0], s_[j][1]);
            *(float2*)&Ps[(w16 + g + 8) * PADK + j * 8 + 2 * q] =
                make_float2(s_[j][2], s_[j][3]);
        }
        __syncwarp();

        // ---- O += P V ----
#pragma unroll
        for (int ks = 0; ks < 8; ks++) {
            uint32_t a[4];
            a[0] = __float_as_uint(Ps[(w16 + g) * PADK + ks * 8 + q]);
            a[1] = __float_as_uint(Ps[(w16 + g + 8) * PADK + ks * 8 + q]);
            a[2] = __float_as_uint(Ps[(w16 + g) * PADK + ks * 8 + q + 4]);
            a[3] = __float_as_uint(Ps[(w16 + g + 8) * PADK + ks * 8 + q + 4]);
#pragma unroll
            for (int j = 0; j < 8; j++) {
                const uint32_t b0 = __float_as_uint(Vt[(j * 8 + g) * PADK + ks * 8 + q]);
                const uint32_t b1 = __float_as_uint(Vt[(j * 8 + g) * PADK + ks * 8 + q + 4]);
                mma_tf32_b(o_[j], a, b0, b1);
            }
        }

        if (kt + 1 < nkt) {
            __syncthreads();   // PV reads of Vt done everywhere
#pragma unroll
            for (int i = 0; i < 4; i++) {
                Vt[(vqr * 16 + i * 4 + 0) * PADK + vr] = vreg[i].x;
                Vt[(vqr * 16 + i * 4 + 1) * PADK + vr] = vreg[i].y;
                Vt[(vqr * 16 + i * 4 + 2) * PADK + vr] = vreg[i].z;
                Vt[(vqr * 16 + i * 4 + 3) * PADK + vr] = vreg[i].w;
            }
            asm volatile("cp.async.wait_group 0;" ::: "memory");
            __syncthreads();   // next tile's K + Vt visible
        }
    }

    // ---- epilogue: normalize, round to tf32, store head-interleaved ----
    const int b = bh >> 4, h = bh & 15;
    const float inv0 = 1.f / l0, inv1 = 1.f / l1;
    const int t0 = qt * 128 + w16 + g;
    float* dst0 = g_o + ((size_t)(b * T_ + t0)) * D_ + h * 64;
    float* dst1 = g_o + ((size_t)(b * T_ + t0 + 8)) * D_ + h * 64;
#pragma unroll
    for (int j = 0; j < 8; j++) {
        *(float2*)(dst0 + j * 8 + 2 * q) =
            make_float2(rna_tf32(o_[j][0] * inv0), rna_tf32(o_[j][1] * inv0));
        *(float2*)(dst1 + j * 8 + 2 * q) =
            make_float2(rna_tf32(o_[j][2] * inv1), rna_tf32(o_[j][3] * inv1));
    }
}

// ---------------------------------------------------------------------------
// Launch
// ---------------------------------------------------------------------------
extern "C" void kernel_launch(void* const* d_in, const int* in_sizes, int n_in,
                              void* d_out, int out_size) {
    const float* x  = (const float*)d_in[0];
    const float* Wk = (const float*)d_in[1];
    const float* Wq = (const float*)d_in[2];
    const float* Wv = (const float*)d_in[3];
    const float* Wp = (const float*)d_in[4];
    const float* bp = (const float*)d_in[5];
    float* out = (float*)d_out;

    float *qp, *kp, *vp, *op, *xr, *wr;
    cudaGetSymbolAddress((void**)&qp, g_q);
    cudaGetSymbolAddress((void**)&kp, g_k);
    cudaGetSymbolAddress((void**)&vp, g_v);
    cudaGetSymbolAddress((void**)&op, g_o);
    cudaGetSymbolAddress((void**)&xr, g_xr);
    cudaGetSymbolAddress((void**)&wr, g_wr);

    const int gemm_smem = 2 * BUF_F * sizeof(float);  // 73728
    cudaFuncSetAttribute(gemm_mma<0>, cudaFuncAttributeMaxDynamicSharedMemorySize, gemm_smem);
    cudaFuncSetAttribute(gemm_mma<1>, cudaFuncAttributeMaxDynamicSharedMemorySize, gemm_smem);

    const int NX = B_ * T_ * D_;
    const int NW = D_ * D_;

    dim3 gg(D_ / 128, M_ / 128);

    // QKV projections (tf32 mma.sync), outputs pre-rounded to tf32
    round_tf32<<<NX / 1024, 256>>>(x, xr);
    round_tf32<<<NW / 1024, 256>>>(Wk, wr);
    gemm_mma<0><<<gg, 256, gemm_smem>>>(xr, wr, kp, nullptr);
    round_tf32<<<NW / 1024, 256>>>(Wq, wr);
    gemm_mma<0><<<gg, 256, gemm_smem>>>(xr, wr, qp, nullptr);
    round_tf32<<<NW / 1024, 256>>>(Wv, wr);
    gemm_mma<0><<<gg, 256, gemm_smem>>>(xr, wr, vp, nullptr);

    // tensor-core flash attention (output pre-rounded to tf32)
    const int fl_smem = (2 * KS_F + KS_F + 128 * PADK) * sizeof(float);  // 87040
    cudaFuncSetAttribute(flash_mma, cudaFuncAttributeMaxDynamicSharedMemorySize, fl_smem);
    flash_mma<<<dim3(T_ / 128, B_ * H_), 256, fl_smem>>>();

    // output projection (consumes pre-rounded g_o directly)
    round_tf32<<<NW / 1024, 256>>>(Wp, wr);
    gemm_mma<1><<<gg, 256, gemm_smem>>>(op, wr, out, bp);
}

// round 6
// speedup vs baseline: 3.3034x; 1.0088x over previous
#include <cuda_runtime.h>
#include <cstdint>

// Problem constants
#define B_  4
#define T_  2048
#define D_  1024
#define H_  16
#define HD_ 64
#define M_  (B_*T_)   // 8192

// Scratch buffers
__device__ float g_q[(size_t)B_*H_*T_*HD_];
__device__ float g_k[(size_t)B_*H_*T_*HD_];
__device__ float g_v[(size_t)B_*H_*T_*HD_];
__device__ float g_o[(size_t)B_*T_*D_];
__device__ float g_xr[(size_t)B_*T_*D_];   // tf32-rounded activations
__device__ float g_wr[(size_t)D_*D_];      // tf32-rounded weight (reused)

// ---------------------------------------------------------------------------
// helpers
// ---------------------------------------------------------------------------
__device__ __forceinline__ uint32_t smem_u32(const void* p) {
    uint32_t a;
    asm("{ .reg .u64 t; cvta.to.shared.u64 t, %1; cvt.u32.u64 %0, t; }"
        : "=r"(a) : "l"(p));
    return a;
}

__device__ __forceinline__ void cp_async16(uint32_t dst, const void* src) {
    asm volatile("cp.async.cg.shared.global [%0], [%1], 16;" :: "r"(dst), "l"(src));
}

__device__ __forceinline__ void mma_tf32(float* c, const uint32_t* a, const uint32_t* b) {
    asm volatile(
        "mma.sync.aligned.m16n8k8.row.col.f32.tf32.tf32.f32 "
        "{%0,%1,%2,%3}, {%4,%5,%6,%7}, {%8,%9}, {%0,%1,%2,%3};"
        : "+f"(c[0]), "+f"(c[1]), "+f"(c[2]), "+f"(c[3])
        : "r"(a[0]), "r"(a[1]), "r"(a[2]), "r"(a[3]), "r"(b[0]), "r"(b[1]));
}

__device__ __forceinline__ void mma_tf32_b(float* c, const uint32_t* a,
                                           uint32_t b0, uint32_t b1) {
    asm volatile(
        "mma.sync.aligned.m16n8k8.row.col.f32.tf32.tf32.f32 "
        "{%0,%1,%2,%3}, {%4,%5,%6,%7}, {%8,%9}, {%0,%1,%2,%3};"
        : "+f"(c[0]), "+f"(c[1]), "+f"(c[2]), "+f"(c[3])
        : "r"(a[0]), "r"(a[1]), "r"(a[2]), "r"(a[3]), "r"(b0), "r"(b1));
}

__device__ __forceinline__ float rna_tf32(float x) {
    uint32_t u;
    asm("cvt.rna.tf32.f32 %0, %1;" : "=r"(u) : "f"(x));
    return __uint_as_float(u);
}

// ---------------------------------------------------------------------------
// tf32 pre-rounding: y[i] = round_rna_tf32(x[i]), vectorized x4
// ---------------------------------------------------------------------------
__global__ void __launch_bounds__(256) round_tf32(const float* __restrict__ x,
                                                  float* __restrict__ y) {
    const size_t i = ((size_t)blockIdx.x * 256 + threadIdx.x) * 4;
    float4 v = *(const float4*)(x + i);
    float4 o;
    o.x = rna_tf32(v.x); o.y = rna_tf32(v.y);
    o.z = rna_tf32(v.z); o.w = rna_tf32(v.w);
    *(float4*)(y + i) = o;
}

// ---------------------------------------------------------------------------
// mma.sync tf32 GEMM v2: out = A[8192,1024] @ W[1024,1024]^T
// CTA 128x128, 4 warps (2x2), warp tile 64x64, BK=32,
// 3-stage cp.async pipeline with ONE __syncthreads per k-step.
// MODE 0: scatter to [B*H][T][HD], rounded to tf32; MODE 1: row-major + bias
// ---------------------------------------------------------------------------
#define SROW   36
#define STG_F  (128 * SROW)      // floats per A or B tile  = 4608
#define STAGE_F (2 * STG_F)      // floats per stage (A+B)  = 9216
#define GSMEM  (3 * STAGE_F * 4) // bytes, 3 stages         = 110592

template<int MODE>
__global__ void __launch_bounds__(128) gemm_mma(const float* __restrict__ A,
                                                const float* __restrict__ W,
                                                float* __restrict__ out,
                                                const float* __restrict__ bias) {
    extern __shared__ float sm[];
    const int tid  = threadIdx.x;
    const int lane = tid & 31;
    const int wid  = tid >> 5;
    const int wm   = wid >> 1;       // 0..1
    const int wn   = wid & 1;        // 0..1
    const int bx = blockIdx.x;       // N tile (8)
    const int by = blockIdx.y;       // M tile (64)

    float c[4][8][4];
#pragma unroll
    for (int i = 0; i < 4; i++)
#pragma unroll
        for (int j = 0; j < 8; j++)
#pragma unroll
            for (int k = 0; k < 4; k++) c[i][j][k] = 0.f;

    // gmem->smem geometry: 128 threads, each 8x16B for A + 8x16B for B per stage
    const int lr = tid >> 3;     // 0..15
    const int ls = tid & 7;      // 16B segment in 128B row
    const float* Ag = A + (size_t)(by * 128 + lr) * 1024 + ls * 4;
    const float* Wg = W + (size_t)(bx * 128 + lr) * 1024 + ls * 4;

    const uint32_t sbase = smem_u32(sm);
    const uint32_t ldst  = sbase + (lr * SROW + ls * 4) * 4;

    auto load_tile = [&](int kt, int s) {
        const uint32_t aB = ldst + (uint32_t)s * (STAGE_F * 4);
        const uint32_t bB = aB + STG_F * 4;
        const float* Ak = Ag + kt * 32;
        const float* Wk = Wg + kt * 32;
#pragma unroll
        for (int i = 0; i < 8; i++) {
            cp_async16(aB + i * 16 * (SROW * 4), Ak + (size_t)i * 16 * 1024);
            cp_async16(bB + i * 16 * (SROW * 4), Wk + (size_t)i * 16 * 1024);
        }
        asm volatile("cp.async.commit_group;" ::: "memory");
    };

    load_tile(0, 0);
    load_tile(1, 1);

    const int g = lane >> 2;     // 0..7
    const int q = lane & 3;      // 0..3

    int s = 0, sl = 2;
    for (int kt = 0; kt < 32; kt++) {
        if (kt < 31) {
            asm volatile("cp.async.wait_group 1;" ::: "memory");
        } else {
            asm volatile("cp.async.wait_group 0;" ::: "memory");
        }
        __syncthreads();   // stage s fully arrived; all warps done reading stage sl

        if (kt + 2 < 32) {
            load_tile(kt + 2, sl);
            sl = (sl == 2) ? 0 : sl + 1;
        }

        const uint32_t* As = (const uint32_t*)(sm + s * STAGE_F) +
                             (wm * 64 + g) * SROW;
        const uint32_t* Bs = (const uint32_t*)(sm + s * STAGE_F + STG_F) +
                             (wn * 64 + g) * SROW;
#pragma unroll
        for (int ks = 0; ks < 4; ks++) {
            const int k0 = ks * 8 + q;
            uint32_t a[4][4], b[8][2];
#pragma unroll
            for (int mm = 0; mm < 4; mm++) {
                a[mm][0] = As[(mm * 16)     * SROW + k0];
                a[mm][1] = As[(mm * 16 + 8) * SROW + k0];
                a[mm][2] = As[(mm * 16)     * SROW + k0 + 4];
                a[mm][3] = As[(mm * 16 + 8) * SROW + k0 + 4];
            }
#pragma unroll
            for (int nn = 0; nn < 8; nn++) {
                b[nn][0] = Bs[(nn * 8) * SROW + k0];
                b[nn][1] = Bs[(nn * 8) * SROW + k0 + 4];
            }
#pragma unroll
            for (int mm = 0; mm < 4; mm++)
#pragma unroll
                for (int nn = 0; nn < 8; nn++)
                    mma_tf32(c[mm][nn], a[mm], b[nn]);
        }
        s = (s == 2) ? 0 : s + 1;
        // no trailing barrier: next iteration's sync protects stage reuse
    }

    // epilogue
    const int rbase = by * 128 + wm * 64 + g;
    const int cbase = bx * 128 + wn * 64 + 2 * q;
#pragma unroll
    for (int mm = 0; mm < 4; mm++) {
        const int r0 = rbase + mm * 16;
#pragma unroll
        for (int nn = 0; nn < 8; nn++) {
            const int cc = cbase + nn * 8;
            if (MODE == 0) {
                const int h = cc >> 6, d = cc & 63;
                const int b = r0 >> 11, t = r0 & 2047;
                float* dst = out + (((size_t)(b * H_ + h)) * T_ + t) * HD_ + d;
                *(float2*)dst =
                    make_float2(rna_tf32(c[mm][nn][0]), rna_tf32(c[mm][nn][1]));
                *(float2*)(dst + 8 * HD_) =
                    make_float2(rna_tf32(c[mm][nn][2]), rna_tf32(c[mm][nn][3]));
            } else {
                float2 bb = *(const float2*)(bias + cc);
                float* dst = out + (size_t)r0 * 1024 + cc;
                *(float2*)dst = make_float2(c[mm][nn][0] + bb.x, c[mm][nn][1] + bb.y);
                *(float2*)(dst + 8 * 1024) =
                    make_float2(c[mm][nn][2] + bb.x, c[mm][nn][3] + bb.y);
            }
        }
    }
}

// ---------------------------------------------------------------------------
// Tensor-core flash attention (causal), tf32 mma.sync. (unchanged, known good)
// ---------------------------------------------------------------------------
#define PADK 68
#define KS_F (64 * PADK)

__global__ void __launch_bounds__(256) flash_mma() {
    extern __shared__ float sm[];
    float* Ks = sm;                       // [2][64][PADK] key-major
    float* Vt = sm + 2 * KS_F;            // [64][PADK]  (d, key)
    float* Ps = sm + 3 * KS_F;            // [128][PADK] (staging Q, then P)

    const int tid = threadIdx.x, lane = tid & 31, wid = tid >> 5;
    const int g = lane >> 2, q = lane & 3;
    const int qt = blockIdx.x, bh = blockIdx.y;
    const int w16 = wid * 16;

    const float* Qg = g_q + (size_t)bh * T_ * HD_ + (size_t)qt * 128 * HD_;
    const float* Kg = g_k + (size_t)bh * T_ * HD_;
    const float* Vg = g_v + (size_t)bh * T_ * HD_;

    const uint32_t sb  = smem_u32(sm);
    const uint32_t VtB = sb + 2 * KS_F * 4;
    const uint32_t PsB = VtB + KS_F * 4;

    {
        const int row = tid >> 1, segb = (tid & 1) * 8;
#pragma unroll
        for (int i = 0; i < 8; i++)
            cp_async16(PsB + (row * PADK + (segb + i) * 4) * 4,
                       Qg + row * 64 + (segb + i) * 4);
    }
#pragma unroll
    for (int i = 0; i < 4; i++) {
        const int idx = tid + i * 256;
        cp_async16(sb + ((idx >> 4) * PADK + (idx & 15) * 4) * 4,
                   Kg + (idx >> 4) * 64 + (idx & 15) * 4);
    }
    asm volatile("cp.async.commit_group;" ::: "memory");

    const int vr = tid & 63, vqr = tid >> 6;
    float4 vreg[4];
#pragma unroll
    for (int i = 0; i < 4; i++)
        vreg[i] = *(const float4*)(Vg + vr * 64 + vqr * 16 + i * 4);

    asm volatile("cp.async.wait_group 0;" ::: "memory");
    __syncthreads();

    uint32_t qf[8][4];
#pragma unroll
    for (int ks = 0; ks < 8; ks++) {
        qf[ks][0] = __float_as_uint(Ps[(w16 + g) * PADK + ks * 8 + q] * 0.125f);
        qf[ks][1] = __float_as_uint(Ps[(w16 + g + 8) * PADK + ks * 8 + q] * 0.125f);
        qf[ks][2] = __float_as_uint(Ps[(w16 + g) * PADK + ks * 8 + q + 4] * 0.125f);
        qf[ks][3] = __float_as_uint(Ps[(w16 + g + 8) * PADK + ks * 8 + q + 4] * 0.125f);
    }
    __syncthreads();

#pragma unroll
    for (int i = 0; i < 4; i++) {
        Vt[(vqr * 16 + i * 4 + 0) * PADK + vr] = vreg[i].x;
        Vt[(vqr * 16 + i * 4 + 1) * PADK + vr] = vreg[i].y;
        Vt[(vqr * 16 + i * 4 + 2) * PADK + vr] = vreg[i].z;
        Vt[(vqr * 16 + i * 4 + 3) * PADK + vr] = vreg[i].w;
    }
    __syncthreads();

    float o_[8][4];
#pragma unroll
    for (int j = 0; j < 8; j++)
#pragma unroll
        for (int k = 0; k < 4; k++) o_[j][k] = 0.f;
    float m0 = -1e30f, m1 = -1e30f, l0 = 0.f, l1 = 0.f;

    const int nkt = 2 * qt + 2;
    for (int kt = 0; kt < nkt; kt++) {
        const int s = kt & 1;

        if (kt + 1 < nkt) {
            const float* Kn = Kg + (size_t)(kt + 1) * 64 * 64;
#pragma unroll
            for (int i = 0; i < 4; i++) {
                const int idx = tid + i * 256;
                cp_async16(sb + ((s ^ 1) * KS_F + (idx >> 4) * PADK + (idx & 15) * 4) * 4,
                           Kn + (idx >> 4) * 64 + (idx & 15) * 4);
            }
            asm volatile("cp.async.commit_group;" ::: "memory");
            const float* Vn = Vg + (size_t)(kt + 1) * 64 * 64;
#pragma unroll
            for (int i = 0; i < 4; i++)
                vreg[i] = *(const float4*)(Vn + vr * 64 + vqr * 16 + i * 4);
        }

        float s_[8][4];
#pragma unroll
        for (int j = 0; j < 8; j++)
#pragma unroll
            for (int k = 0; k < 4; k++) s_[j][k] = 0.f;

        const float* Kb = Ks + s * KS_F;
#pragma unroll
        for (int ks = 0; ks < 8; ks++) {
#pragma unroll
            for (int j = 0; j < 8; j++) {
                const uint32_t b0 = __float_as_uint(Kb[(j * 8 + g) * PADK + ks * 8 + q]);
                const uint32_t b1 = __float_as_uint(Kb[(j * 8 + g) * PADK + ks * 8 + q + 4]);
                mma_tf32_b(s_[j], qf[ks], b0, b1);
            }
        }

        if (kt >= 2 * qt) {
            const int kb = kt * 64;
            const int r0 = qt * 128 + w16 + g, r1 = r0 + 8;
#pragma unroll
            for (int j = 0; j < 8; j++) {
                const int k0 = kb + j * 8 + 2 * q;
                if (k0 > r0)     s_[j][0] = -1e30f;
                if (k0 + 1 > r0) s_[j][1] = -1e30f;
                if (k0 > r1)     s_[j][2] = -1e30f;
                if (k0 + 1 > r1) s_[j][3] = -1e30f;
            }
        }

        float mx0 = -1e30f, mx1 = -1e30f;
#pragma unroll
        for (int j = 0; j < 8; j++) {
            mx0 = fmaxf(mx0, fmaxf(s_[j][0], s_[j][1]));
            mx1 = fmaxf(mx1, fmaxf(s_[j][2], s_[j][3]));
        }
        mx0 = fmaxf(mx0, __shfl_xor_sync(0xffffffffu, mx0, 1));
        mx0 = fmaxf(mx0, __shfl_xor_sync(0xffffffffu, mx0, 2));
        mx1 = fmaxf(mx1, __shfl_xor_sync(0xffffffffu, mx1, 1));
        mx1 = fmaxf(mx1, __shfl_xor_sync(0xffffffffu, mx1, 2));

        const float mn0 = fmaxf(m0, mx0), mn1 = fmaxf(m1, mx1);
        const float ex0 = __expf(m0 - mn0), ex1 = __expf(m1 - mn1);
        float rs0 = 0.f, rs1 = 0.f;
#pragma unroll
        for (int j = 0; j < 8; j++) {
            s_[j][0] = rna_tf32(__expf(s_[j][0] - mn0));
            s_[j][1] = rna_tf32(__expf(s_[j][1] - mn0));
            s_[j][2] = rna_tf32(__expf(s_[j][2] - mn1));
            s_[j][3] = rna_tf32(__expf(s_[j][3] - mn1));
            rs0 += s_[j][0] + s_[j][1];
            rs1 += s_[j][2] + s_[j][3];
        }
        rs0 += __shfl_xor_sync(0xffffffffu, rs0, 1);
        rs0 += __shfl_xor_sync(0xffffffffu, rs0, 2);
        rs1 += __shfl_xor_sync(0xffffffffu, rs1, 1);
        rs1 += __shfl_xor_sync(0xffffffffu, rs1, 2);
        l0 = l0 * ex0 + rs0;  m0 = mn0;
        l1 = l1 * ex1 + rs1;  m1 = mn1;
#pragma unroll
        for (int j = 0; j < 8; j++) {
            o_[j][0] *= ex0; o_[j][1] *= ex0;
            o_[j][2] *= ex1; o_[j][3] *= ex1;
        }

#pragma unroll
        for (int j = 0; j < 8; j++) {
            *(float2*)&Ps[(w16 + g) * PADK + j * 8 + 2 * q] =
                make_float2(s_[j][0], s_[j][1]);
            *(float2*)&Ps[(w16 + g + 8) * PADK + j * 8 + 2 * q] =
                make_float2(s_[j][2], s_[j][3]);
        }
        __syncwarp();

#pragma unroll
        for (int ks = 0; ks < 8; ks++) {
            uint32_t a[4];
            a[0] = __float_as_uint(Ps[(w16 + g) * PADK + ks * 8 + q]);
            a[1] = __float_as_uint(Ps[(w16 + g + 8) * PADK + ks * 8 + q]);
            a[2] = __float_as_uint(Ps[(w16 + g) * PADK + ks * 8 + q + 4]);
            a[3] = __float_as_uint(Ps[(w16 + g + 8) * PADK + ks * 8 + q + 4]);
#pragma unroll
            for (int j = 0; j < 8; j++) {
                const uint32_t b0 = __float_as_uint(Vt[(j * 8 + g) * PADK + ks * 8 + q]);
                const uint32_t b1 = __float_as_uint(Vt[(j * 8 + g) * PADK + ks * 8 + q + 4]);
                mma_tf32_b(o_[j], a, b0, b1);
            }
        }

        if (kt + 1 < nkt) {
            __syncthreads();
#pragma unroll
            for (int i = 0; i < 4; i++) {
                Vt[(vqr * 16 + i * 4 + 0) * PADK + vr] = vreg[i].x;
                Vt[(vqr * 16 + i * 4 + 1) * PADK + vr] = vreg[i].y;
                Vt[(vqr * 16 + i * 4 + 2) * PADK + vr] = vreg[i].z;
                Vt[(vqr * 16 + i * 4 + 3) * PADK + vr] = vreg[i].w;
            }
            asm volatile("cp.async.wait_group 0;" ::: "memory");
            __syncthreads();
        }
    }

    const int b = bh >> 4, h = bh & 15;
    const float inv0 = 1.f / l0, inv1 = 1.f / l1;
    const int t0 = qt * 128 + w16 + g;
    float* dst0 = g_o + ((size_t)(b * T_ + t0)) * D_ + h * 64;
    float* dst1 = g_o + ((size_t)(b * T_ + t0 + 8)) * D_ + h * 64;
#pragma unroll
    for (int j = 0; j < 8; j++) {
        *(float2*)(dst0 + j * 8 + 2 * q) =
            make_float2(rna_tf32(o_[j][0] * inv0), rna_tf32(o_[j][1] * inv0));
        *(float2*)(dst1 + j * 8 + 2 * q) =
            make_float2(rna_tf32(o_[j][2] * inv1), rna_tf32(o_[j][3] * inv1));
    }
}

// ---------------------------------------------------------------------------
// Launch
// ---------------------------------------------------------------------------
extern "C" void kernel_launch(void* const* d_in, const int* in_sizes, int n_in,
                              void* d_out, int out_size) {
    const float* x  = (const float*)d_in[0];
    const float* Wk = (const float*)d_in[1];
    const float* Wq = (const float*)d_in[2];
    const float* Wv = (const float*)d_in[3];
    const float* Wp = (const float*)d_in[4];
    const float* bp = (const float*)d_in[5];
    float* out = (float*)d_out;

    float *qp, *kp, *vp, *op, *xr, *wr;
    cudaGetSymbolAddress((void**)&qp, g_q);
    cudaGetSymbolAddress((void**)&kp, g_k);
    cudaGetSymbolAddress((void**)&vp, g_v);
    cudaGetSymbolAddress((void**)&op, g_o);
    cudaGetSymbolAddress((void**)&xr, g_xr);
    cudaGetSymbolAddress((void**)&wr, g_wr);

    cudaFuncSetAttribute(gemm_mma<0>, cudaFuncAttributeMaxDynamicSharedMemorySize, GSMEM);
    cudaFuncSetAttribute(gemm_mma<1>, cudaFuncAttributeMaxDynamicSharedMemorySize, GSMEM);

    const int NX = B_ * T_ * D_;
    const int NW = D_ * D_;

    dim3 gg(D_ / 128, M_ / 128);

    // QKV projections (tf32 mma.sync), outputs pre-rounded to tf32
    round_tf32<<<NX / 1024, 256>>>(x, xr);
    round_tf32<<<NW / 1024, 256>>>(Wk, wr);
    gemm_mma<0><<<gg, 128, GSMEM>>>(xr, wr, kp, nullptr);
    round_tf32<<<NW / 1024, 256>>>(Wq, wr);
    gemm_mma<0><<<gg, 128, GSMEM>>>(xr, wr, qp, nullptr);
    round_tf32<<<NW / 1024, 256>>>(Wv, wr);
    gemm_mma<0><<<gg, 128, GSMEM>>>(xr, wr, vp, nullptr);

    // tensor-core flash attention (output pre-rounded to tf32)
    const int fl_smem = (2 * KS_F + KS_F + 128 * PADK) * sizeof(float);  // 87040
    cudaFuncSetAttribute(flash_mma, cudaFuncAttributeMaxDynamicSharedMemorySize, fl_smem);
    flash_mma<<<dim3(T_ / 128, B_ * H_), 256, fl_smem>>>();

    // output projection (consumes pre-rounded g_o directly)
    round_tf32<<<NW / 1024, 256>>>(Wp, wr);
    gemm_mma<1><<<gg, 128, GSMEM>>>(op, wr, out, bp);
}

// round 7
// speedup vs baseline: 3.3276x; 1.0073x over previous
#include <cuda_runtime.h>
#include <cstdint>

// Problem constants
#define B_  4
#define T_  2048
#define D_  1024
#define H_  16
#define HD_ 64
#define M_  (B_*T_)   // 8192

// Scratch buffers
__device__ float g_q[(size_t)B_*H_*T_*HD_];
__device__ float g_k[(size_t)B_*H_*T_*HD_];
__device__ float g_v[(size_t)B_*H_*T_*HD_];
__device__ float g_o[(size_t)B_*T_*D_];
__device__ float g_xr[(size_t)B_*T_*D_];     // tf32-rounded activations
__device__ float g_wr[(size_t)4*D_*D_];      // tf32-rounded weights (k,q,v,p)

// ---------------------------------------------------------------------------
// helpers
// ---------------------------------------------------------------------------
__device__ __forceinline__ uint32_t smem_u32(const void* p) {
    uint32_t a;
    asm("{ .reg .u64 t; cvta.to.shared.u64 t, %1; cvt.u32.u64 %0, t; }"
        : "=r"(a) : "l"(p));
    return a;
}

__device__ __forceinline__ void cp_async16(uint32_t dst, const void* src) {
    asm volatile("cp.async.cg.shared.global [%0], [%1], 16;" :: "r"(dst), "l"(src));
}

__device__ __forceinline__ void mma_tf32(float* c, const uint32_t* a, const uint32_t* b) {
    asm volatile(
        "mma.sync.aligned.m16n8k8.row.col.f32.tf32.tf32.f32 "
        "{%0,%1,%2,%3}, {%4,%5,%6,%7}, {%8,%9}, {%0,%1,%2,%3};"
        : "+f"(c[0]), "+f"(c[1]), "+f"(c[2]), "+f"(c[3])
        : "r"(a[0]), "r"(a[1]), "r"(a[2]), "r"(a[3]), "r"(b[0]), "r"(b[1]));
}

__device__ __forceinline__ void mma_tf32_b(float* c, const uint32_t* a,
                                           uint32_t b0, uint32_t b1) {
    asm volatile(
        "mma.sync.aligned.m16n8k8.row.col.f32.tf32.tf32.f32 "
        "{%0,%1,%2,%3}, {%4,%5,%6,%7}, {%8,%9}, {%0,%1,%2,%3};"
        : "+f"(c[0]), "+f"(c[1]), "+f"(c[2]), "+f"(c[3])
        : "r"(a[0]), "r"(a[1]), "r"(a[2]), "r"(a[3]), "r"(b0), "r"(b1));
}

__device__ __forceinline__ float rna_tf32(float x) {
    uint32_t u;
    asm("cvt.rna.tf32.f32 %0, %1;" : "=r"(u) : "f"(x));
    return __uint_as_float(u);
}

// ---------------------------------------------------------------------------
// tf32 pre-rounding: y[i] = round_rna_tf32(x[i]), vectorized x4
// ---------------------------------------------------------------------------
__global__ void __launch_bounds__(256) round_tf32(const float* __restrict__ x,
                                                  float* __restrict__ y) {
    const size_t i = ((size_t)blockIdx.x * 256 + threadIdx.x) * 4;
    float4 v = *(const float4*)(x + i);
    float4 o;
    o.x = rna_tf32(v.x); o.y = rna_tf32(v.y);
    o.z = rna_tf32(v.z); o.w = rna_tf32(v.w);
    *(float4*)(y + i) = o;
}

// ---------------------------------------------------------------------------
// Shared GEMM body: C(128x128 CTA tile) = A[128,1024] @ W[128,1024]^T
// 4 warps (2x2), warp tile 64x64, BK=32, 3-stage cp.async, 1 barrier/k-step.
// MODE 0: scatter to [B*H][T][HD], rounded tf32; MODE 1: row-major + bias
// ---------------------------------------------------------------------------
#define SROW   36
#define STG_F  (128 * SROW)      // floats per A or B tile  = 4608
#define STAGE_F (2 * STG_F)      // floats per stage (A+B)  = 9216
#define GSMEM  (3 * STAGE_F * 4) // bytes, 3 stages         = 110592

template<int MODE>
__device__ __forceinline__ void gemm_body(const float* __restrict__ A,
                                          const float* __restrict__ W,
                                          float* __restrict__ out,
                                          const float* __restrict__ bias,
                                          float* sm, int bx, int by) {
    const int tid  = threadIdx.x;
    const int lane = tid & 31;
    const int wid  = tid >> 5;
    const int wm   = wid >> 1;
    const int wn   = wid & 1;

    float c[4][8][4];
#pragma unroll
    for (int i = 0; i < 4; i++)
#pragma unroll
        for (int j = 0; j < 8; j++)
#pragma unroll
            for (int k = 0; k < 4; k++) c[i][j][k] = 0.f;

    const int lr = tid >> 3;
    const int ls = tid & 7;
    const float* Ag = A + (size_t)(by * 128 + lr) * 1024 + ls * 4;
    const float* Wg = W + (size_t)(bx * 128 + lr) * 1024 + ls * 4;

    const uint32_t sbase = smem_u32(sm);
    const uint32_t ldst  = sbase + (lr * SROW + ls * 4) * 4;

    auto load_tile = [&](int kt, int s) {
        const uint32_t aB = ldst + (uint32_t)s * (STAGE_F * 4);
        const uint32_t bB = aB + STG_F * 4;
        const float* Ak = Ag + kt * 32;
        const float* Wk = Wg + kt * 32;
#pragma unroll
        for (int i = 0; i < 8; i++) {
            cp_async16(aB + i * 16 * (SROW * 4), Ak + (size_t)i * 16 * 1024);
            cp_async16(bB + i * 16 * (SROW * 4), Wk + (size_t)i * 16 * 1024);
        }
        asm volatile("cp.async.commit_group;" ::: "memory");
    };

    load_tile(0, 0);
    load_tile(1, 1);

    const int g = lane >> 2;
    const int q = lane & 3;

    int s = 0, sl = 2;
    for (int kt = 0; kt < 32; kt++) {
        if (kt < 31) {
            asm volatile("cp.async.wait_group 1;" ::: "memory");
        } else {
            asm volatile("cp.async.wait_group 0;" ::: "memory");
        }
        __syncthreads();

        if (kt + 2 < 32) {
            load_tile(kt + 2, sl);
            sl = (sl == 2) ? 0 : sl + 1;
        }

        const uint32_t* As = (const uint32_t*)(sm + s * STAGE_F) +
                             (wm * 64 + g) * SROW;
        const uint32_t* Bs = (const uint32_t*)(sm + s * STAGE_F + STG_F) +
                             (wn * 64 + g) * SROW;
#pragma unroll
        for (int ks = 0; ks < 4; ks++) {
            const int k0 = ks * 8 + q;
            uint32_t a[4][4], b[8][2];
#pragma unroll
            for (int mm = 0; mm < 4; mm++) {
                a[mm][0] = As[(mm * 16)     * SROW + k0];
                a[mm][1] = As[(mm * 16 + 8) * SROW + k0];
                a[mm][2] = As[(mm * 16)     * SROW + k0 + 4];
                a[mm][3] = As[(mm * 16 + 8) * SROW + k0 + 4];
            }
#pragma unroll
            for (int nn = 0; nn < 8; nn++) {
                b[nn][0] = Bs[(nn * 8) * SROW + k0];
                b[nn][1] = Bs[(nn * 8) * SROW + k0 + 4];
            }
#pragma unroll
            for (int mm = 0; mm < 4; mm++)
#pragma unroll
                for (int nn = 0; nn < 8; nn++)
                    mma_tf32(c[mm][nn], a[mm], b[nn]);
        }
        s = (s == 2) ? 0 : s + 1;
    }

    const int rbase = by * 128 + wm * 64 + g;
    const int cbase = bx * 128 + wn * 64 + 2 * q;
#pragma unroll
    for (int mm = 0; mm < 4; mm++) {
        const int r0 = rbase + mm * 16;
#pragma unroll
        for (int nn = 0; nn < 8; nn++) {
            const int cc = cbase + nn * 8;
            if (MODE == 0) {
                const int h = cc >> 6, d = cc & 63;
                const int b = r0 >> 11, t = r0 & 2047;
                float* dst = out + (((size_t)(b * H_ + h)) * T_ + t) * HD_ + d;
                *(float2*)dst =
                    make_float2(rna_tf32(c[mm][nn][0]), rna_tf32(c[mm][nn][1]));
                *(float2*)(dst + 8 * HD_) =
                    make_float2(rna_tf32(c[mm][nn][2]), rna_tf32(c[mm][nn][3]));
            } else {
                float2 bb = *(const float2*)(bias + cc);
                float* dst = out + (size_t)r0 * 1024 + cc;
                *(float2*)dst = make_float2(c[mm][nn][0] + bb.x, c[mm][nn][1] + bb.y);
                *(float2*)(dst + 8 * 1024) =
                    make_float2(c[mm][nn][2] + bb.x, c[mm][nn][3] + bb.y);
            }
        }
    }
}

// Fused QKV: grid (8, 64, 3); z selects which projection.
__global__ void __launch_bounds__(128) gemm_qkv(const float* __restrict__ A,
                                                const float* __restrict__ Wr,
                                                float* __restrict__ o0,
                                                float* __restrict__ o1,
                                                float* __restrict__ o2) {
    extern __shared__ float sm[];
    const int z = blockIdx.z;
    const float* W = Wr + (size_t)z * D_ * D_;
    float* out = (z == 0) ? o0 : (z == 1) ? o1 : o2;
    gemm_body<0>(A, W, out, nullptr, sm, blockIdx.x, blockIdx.y);
}

// Output projection.
__global__ void __launch_bounds__(128) gemm_out(const float* __restrict__ A,
                                                const float* __restrict__ W,
                                                float* __restrict__ out,
                                                const float* __restrict__ bias) {
    extern __shared__ float sm[];
    gemm_body<1>(A, W, out, bias, sm, blockIdx.x, blockIdx.y);
}

// ---------------------------------------------------------------------------
// Tensor-core flash attention (causal), tf32 mma.sync. (unchanged, known good)
// ---------------------------------------------------------------------------
#define PADK 68
#define KS_F (64 * PADK)

__global__ void __launch_bounds__(256) flash_mma() {
    extern __shared__ float sm[];
    float* Ks = sm;                       // [2][64][PADK] key-major
    float* Vt = sm + 2 * KS_F;            // [64][PADK]  (d, key)
    float* Ps = sm + 3 * KS_F;            // [128][PADK] (staging Q, then P)

    const int tid = threadIdx.x, lane = tid & 31, wid = tid >> 5;
    const int g = lane >> 2, q = lane & 3;
    const int qt = blockIdx.x, bh = blockIdx.y;
    const int w16 = wid * 16;

    const float* Qg = g_q + (size_t)bh * T_ * HD_ + (size_t)qt * 128 * HD_;
    const float* Kg = g_k + (size_t)bh * T_ * HD_;
    const float* Vg = g_v + (size_t)bh * T_ * HD_;

    const uint32_t sb  = smem_u32(sm);
    const uint32_t VtB = sb + 2 * KS_F * 4;
    const uint32_t PsB = VtB + KS_F * 4;

    {
        const int row = tid >> 1, segb = (tid & 1) * 8;
#pragma unroll
        for (int i = 0; i < 8; i++)
            cp_async16(PsB + (row * PADK + (segb + i) * 4) * 4,
                       Qg + row * 64 + (segb + i) * 4);
    }
#pragma unroll
    for (int i = 0; i < 4; i++) {
        const int idx = tid + i * 256;
        cp_async16(sb + ((idx >> 4) * PADK + (idx & 15) * 4) * 4,
                   Kg + (idx >> 4) * 64 + (idx & 15) * 4);
    }
    asm volatile("cp.async.commit_group;" ::: "memory");

    const int vr = tid & 63, vqr = tid >> 6;
    float4 vreg[4];
#pragma unroll
    for (int i = 0; i < 4; i++)
        vreg[i] = *(const float4*)(Vg + vr * 64 + vqr * 16 + i * 4);

    asm volatile("cp.async.wait_group 0;" ::: "memory");
    __syncthreads();

    uint32_t qf[8][4];
#pragma unroll
    for (int ks = 0; ks < 8; ks++) {
        qf[ks][0] = __float_as_uint(Ps[(w16 + g) * PADK + ks * 8 + q] * 0.125f);
        qf[ks][1] = __float_as_uint(Ps[(w16 + g + 8) * PADK + ks * 8 + q] * 0.125f);
        qf[ks][2] = __float_as_uint(Ps[(w16 + g) * PADK + ks * 8 + q + 4] * 0.125f);
        qf[ks][3] = __float_as_uint(Ps[(w16 + g + 8) * PADK + ks * 8 + q + 4] * 0.125f);
    }
    __syncthreads();

#pragma unroll
    for (int i = 0; i < 4; i++) {
        Vt[(vqr * 16 + i * 4 + 0) * PADK + vr] = vreg[i].x;
        Vt[(vqr * 16 + i * 4 + 1) * PADK + vr] = vreg[i].y;
        Vt[(vqr * 16 + i * 4 + 2) * PADK + vr] = vreg[i].z;
        Vt[(vqr * 16 + i * 4 + 3) * PADK + vr] = vreg[i].w;
    }
    __syncthreads();

    float o_[8][4];
#pragma unroll
    for (int j = 0; j < 8; j++)
#pragma unroll
        for (int k = 0; k < 4; k++) o_[j][k] = 0.f;
    float m0 = -1e30f, m1 = -1e30f, l0 = 0.f, l1 = 0.f;

    const int nkt = 2 * qt + 2;
    for (int kt = 0; kt < nkt; kt++) {
        const int s = kt & 1;

        if (kt + 1 < nkt) {
            const float* Kn = Kg + (size_t)(kt + 1) * 64 * 64;
#pragma unroll
            for (int i = 0; i < 4; i++) {
                const int idx = tid + i * 256;
                cp_async16(sb + ((s ^ 1) * KS_F + (idx >> 4) * PADK + (idx & 15) * 4) * 4,
                           Kn + (idx >> 4) * 64 + (idx & 15) * 4);
            }
            asm volatile("cp.async.commit_group;" ::: "memory");
            const float* Vn = Vg + (size_t)(kt + 1) * 64 * 64;
#pragma unroll
            for (int i = 0; i < 4; i++)
                vreg[i] = *(const float4*)(Vn + vr * 64 + vqr * 16 + i * 4);
        }

        float s_[8][4];
#pragma unroll
        for (int j = 0; j < 8; j++)
#pragma unroll
            for (int k = 0; k < 4; k++) s_[j][k] = 0.f;

        const float* Kb = Ks + s * KS_F;
#pragma unroll
        for (int ks = 0; ks < 8; ks++) {
#pragma unroll
            for (int j = 0; j < 8; j++) {
                const uint32_t b0 = __float_as_uint(Kb[(j * 8 + g) * PADK + ks * 8 + q]);
                const uint32_t b1 = __float_as_uint(Kb[(j * 8 + g) * PADK + ks * 8 + q + 4]);
                mma_tf32_b(s_[j], qf[ks], b0, b1);
            }
        }

        if (kt >= 2 * qt) {
            const int kb = kt * 64;
            const int r0 = qt * 128 + w16 + g, r1 = r0 + 8;
#pragma unroll
            for (int j = 0; j < 8; j++) {
                const int k0 = kb + j * 8 + 2 * q;
                if (k0 > r0)     s_[j][0] = -1e30f;
                if (k0 + 1 > r0) s_[j][1] = -1e30f;
                if (k0 > r1)     s_[j][2] = -1e30f;
                if (k0 + 1 > r1) s_[j][3] = -1e30f;
            }
        }

        float mx0 = -1e30f, mx1 = -1e30f;
#pragma unroll
        for (int j = 0; j < 8; j++) {
            mx0 = fmaxf(mx0, fmaxf(s_[j][0], s_[j][1]));
            mx1 = fmaxf(mx1, fmaxf(s_[j][2], s_[j][3]));
        }
        mx0 = fmaxf(mx0, __shfl_xor_sync(0xffffffffu, mx0, 1));
        mx0 = fmaxf(mx0, __shfl_xor_sync(0xffffffffu, mx0, 2));
        mx1 = fmaxf(mx1, __shfl_xor_sync(0xffffffffu, mx1, 1));
        mx1 = fmaxf(mx1, __shfl_xor_sync(0xffffffffu, mx1, 2));

        const float mn0 = fmaxf(m0, mx0), mn1 = fmaxf(m1, mx1);
        const float ex0 = __expf(m0 - mn0), ex1 = __expf(m1 - mn1);
        float rs0 = 0.f, rs1 = 0.f;
#pragma unroll
        for (int j = 0; j < 8; j++) {
            s_[j][0] = rna_tf32(__expf(s_[j][0] - mn0));
            s_[j][1] = rna_tf32(__expf(s_[j][1] - mn0));
            s_[j][2] = rna_tf32(__expf(s_[j][2] - mn1));
            s_[j][3] = rna_tf32(__expf(s_[j][3] - mn1));
            rs0 += s_[j][0] + s_[j][1];
            rs1 += s_[j][2] + s_[j][3];
        }
        rs0 += __shfl_xor_sync(0xffffffffu, rs0, 1);
        rs0 += __shfl_xor_sync(0xffffffffu, rs0, 2);
        rs1 += __shfl_xor_sync(0xffffffffu, rs1, 1);
        rs1 += __shfl_xor_sync(0xffffffffu, rs1, 2);
        l0 = l0 * ex0 + rs0;  m0 = mn0;
        l1 = l1 * ex1 + rs1;  m1 = mn1;
#pragma unroll
        for (int j = 0; j < 8; j++) {
            o_[j][0] *= ex0; o_[j][1] *= ex0;
            o_[j][2] *= ex1; o_[j][3] *= ex1;
        }

#pragma unroll
        for (int j = 0; j < 8; j++) {
            *(float2*)&Ps[(w16 + g) * PADK + j * 8 + 2 * q] =
                make_float2(s_[j][0], s_[j][1]);
            *(float2*)&Ps[(w16 + g + 8) * PADK + j * 8 + 2 * q] =
                make_float2(s_[j][2], s_[j][3]);
        }
        __syncwarp();

#pragma unroll
        for (int ks = 0; ks < 8; ks++) {
            uint32_t a[4];
            a[0] = __float_as_uint(Ps[(w16 + g) * PADK + ks * 8 + q]);
            a[1] = __float_as_uint(Ps[(w16 + g + 8) * PADK + ks * 8 + q]);
            a[2] = __float_as_uint(Ps[(w16 + g) * PADK + ks * 8 + q + 4]);
            a[3] = __float_as_uint(Ps[(w16 + g + 8) * PADK + ks * 8 + q + 4]);
#pragma unroll
            for (int j = 0; j < 8; j++) {
                const uint32_t b0 = __float_as_uint(Vt[(j * 8 + g) * PADK + ks * 8 + q]);
                const uint32_t b1 = __float_as_uint(Vt[(j * 8 + g) * PADK + ks * 8 + q + 4]);
                mma_tf32_b(o_[j], a, b0, b1);
            }
        }

        if (kt + 1 < nkt) {
            __syncthreads();
#pragma unroll
            for (int i = 0; i < 4; i++) {
                Vt[(vqr * 16 + i * 4 + 0) * PADK + vr] = vreg[i].x;
                Vt[(vqr * 16 + i * 4 + 1) * PADK + vr] = vreg[i].y;
                Vt[(vqr * 16 + i * 4 + 2) * PADK + vr] = vreg[i].z;
                Vt[(vqr * 16 + i * 4 + 3) * PADK + vr] = vreg[i].w;
            }
            asm volatile("cp.async.wait_group 0;" ::: "memory");
            __syncthreads();
        }
    }

    const int b = bh >> 4, h = bh & 15;
    const float inv0 = 1.f / l0, inv1 = 1.f / l1;
    const int t0 = qt * 128 + w16 + g;
    float* dst0 = g_o + ((size_t)(b * T_ + t0)) * D_ + h * 64;
    float* dst1 = g_o + ((size_t)(b * T_ + t0 + 8)) * D_ + h * 64;
#pragma unroll
    for (int j = 0; j < 8; j++) {
        *(float2*)(dst0 + j * 8 + 2 * q) =
            make_float2(rna_tf32(o_[j][0] * inv0), rna_tf32(o_[j][1] * inv0));
        *(float2*)(dst1 + j * 8 + 2 * q) =
            make_float2(rna_tf32(o_[j][2] * inv1), rna_tf32(o_[j][3] * inv1));
    }
}

// ---------------------------------------------------------------------------
// Launch.  Order chosen so launch index 5 (ncu -s 5 -c 1) is gemm_qkv.
// ---------------------------------------------------------------------------
extern "C" void kernel_launch(void* const* d_in, const int* in_sizes, int n_in,
                              void* d_out, int out_size) {
    const float* x  = (const float*)d_in[0];
    const float* Wk = (const float*)d_in[1];
    const float* Wq = (const float*)d_in[2];
    const float* Wv = (const float*)d_in[3];
    const float* Wp = (const float*)d_in[4];
    const float* bp = (const float*)d_in[5];
    float* out = (float*)d_out;

    float *qp, *kp, *vp, *op, *xr, *wr;
    cudaGetSymbolAddress((void**)&qp, g_q);
    cudaGetSymbolAddress((void**)&kp, g_k);
    cudaGetSymbolAddress((void**)&vp, g_v);
    cudaGetSymbolAddress((void**)&op, g_o);
    cudaGetSymbolAddress((void**)&xr, g_xr);
    cudaGetSymbolAddress((void**)&wr, g_wr);

    cudaFuncSetAttribute(gemm_qkv, cudaFuncAttributeMaxDynamicSharedMemorySize, GSMEM);
    cudaFuncSetAttribute(gemm_out, cudaFuncAttributeMaxDynamicSharedMemorySize, GSMEM);

    const int NX = B_ * T_ * D_;
    const int NW = D_ * D_;

    // launches 0-4: tf32 rounding (x, Wk, Wq, Wv, Wp)
    round_tf32<<<NX / 1024, 256>>>(x, xr);
    round_tf32<<<NW / 1024, 256>>>(Wk, wr + 0 * (size_t)NW);
    round_tf32<<<NW / 1024, 256>>>(Wq, wr + 1 * (size_t)NW);
    round_tf32<<<NW / 1024, 256>>>(Wv, wr + 2 * (size_t)NW);
    round_tf32<<<NW / 1024, 256>>>(Wp, wr + 3 * (size_t)NW);

    // launch 5: fused QKV projections (ncu capture target)
    gemm_qkv<<<dim3(D_ / 128, M_ / 128, 3), 128, GSMEM>>>(xr, wr, kp, qp, vp);

    // launch 6: tensor-core flash attention (output pre-rounded to tf32)
    const int fl_smem = (2 * KS_F + KS_F + 128 * PADK) * sizeof(float);  // 87040
    cudaFuncSetAttribute(flash_mma, cudaFuncAttributeMaxDynamicSharedMemorySize, fl_smem);
    flash_mma<<<dim3(T_ / 128, B_ * H_), 256, fl_smem>>>();

    // launch 7: output projection
    gemm_out<<<dim3(D_ / 128, M_ / 128), 128, GSMEM>>>(op, wr + 3 * (size_t)NW, out, bp);
}

// round 8
// speedup vs baseline: 3.3425x; 1.0045x over previous
#include <cuda_runtime.h>
#include <cstdint>

// Problem constants
#define B_  4
#define T_  2048
#define D_  1024
#define H_  16
#define HD_ 64
#define M_  (B_*T_)   // 8192

// Scratch buffers
__device__ float g_q[(size_t)B_*H_*T_*HD_];
__device__ float g_k[(size_t)B_*H_*T_*HD_];
__device__ float g_v[(size_t)B_*H_*T_*HD_];
__device__ float g_o[(size_t)B_*T_*D_];
__device__ float g_xr[(size_t)B_*T_*D_];     // tf32-rounded activations
__device__ float g_wr[(size_t)4*D_*D_];      // tf32-rounded weights (k,q,v,p)

// ---------------------------------------------------------------------------
// helpers
// ---------------------------------------------------------------------------
__device__ __forceinline__ uint32_t smem_u32(const void* p) {
    uint32_t a;
    asm("{ .reg .u64 t; cvta.to.shared.u64 t, %1; cvt.u32.u64 %0, t; }"
        : "=r"(a) : "l"(p));
    return a;
}

__device__ __forceinline__ void cp_async16(uint32_t dst, const void* src) {
    asm volatile("cp.async.cg.shared.global [%0], [%1], 16;" :: "r"(dst), "l"(src));
}

__device__ __forceinline__ void mma_tf32(float* c, const uint32_t* a, const uint32_t* b) {
    asm volatile(
        "mma.sync.aligned.m16n8k8.row.col.f32.tf32.tf32.f32 "
        "{%0,%1,%2,%3}, {%4,%5,%6,%7}, {%8,%9}, {%0,%1,%2,%3};"
        : "+f"(c[0]), "+f"(c[1]), "+f"(c[2]), "+f"(c[3])
        : "r"(a[0]), "r"(a[1]), "r"(a[2]), "r"(a[3]), "r"(b[0]), "r"(b[1]));
}

__device__ __forceinline__ void mma_tf32_b(float* c, const uint32_t* a,
                                           uint32_t b0, uint32_t b1) {
    asm volatile(
        "mma.sync.aligned.m16n8k8.row.col.f32.tf32.tf32.f32 "
        "{%0,%1,%2,%3}, {%4,%5,%6,%7}, {%8,%9}, {%0,%1,%2,%3};"
        : "+f"(c[0]), "+f"(c[1]), "+f"(c[2]), "+f"(c[3])
        : "r"(a[0]), "r"(a[1]), "r"(a[2]), "r"(a[3]), "r"(b0), "r"(b1));
}

__device__ __forceinline__ float rna_tf32(float x) {
    uint32_t u;
    asm("cvt.rna.tf32.f32 %0, %1;" : "=r"(u) : "f"(x));
    return __uint_as_float(u);
}

// ---------------------------------------------------------------------------
// tf32 pre-rounding
// ---------------------------------------------------------------------------
__global__ void __launch_bounds__(256) round_tf32(const float* __restrict__ x,
                                                  float* __restrict__ y) {
    const size_t i = ((size_t)blockIdx.x * 256 + threadIdx.x) * 4;
    float4 v = *(const float4*)(x + i);
    float4 o;
    o.x = rna_tf32(v.x); o.y = rna_tf32(v.y);
    o.z = rna_tf32(v.z); o.w = rna_tf32(v.w);
    *(float4*)(y + i) = o;
}

// fused 4-weight rounding: grid (NW/1024, 4); y selects source
struct WPtrs { const float* w[4]; };
__global__ void __launch_bounds__(256) round_w4(WPtrs ws, float* __restrict__ y) {
    const int z = blockIdx.y;
    const float* src = ws.w[z];
    float* dst = y + (size_t)z * D_ * D_;
    const size_t i = ((size_t)blockIdx.x * 256 + threadIdx.x) * 4;
    float4 v = *(const float4*)(src + i);
    float4 o;
    o.x = rna_tf32(v.x); o.y = rna_tf32(v.y);
    o.z = rna_tf32(v.z); o.w = rna_tf32(v.w);
    *(float4*)(dst + i) = o;
}

// ---------------------------------------------------------------------------
// GEMM body: C(128x128) = A[128,1024] @ W[128,1024]^T
// 4 warps (2x2), warp tile 64x64, BK=32, 3-stage cp.async, 1 barrier/k-step,
// fragment DOUBLE-BUFFERING: ks+1 fragment LDS issued before ks MMA block.
// ---------------------------------------------------------------------------
#define SROW   36
#define STG_F  (128 * SROW)
#define STAGE_F (2 * STG_F)
#define GSMEM  (3 * STAGE_F * 4)   // 110592 B

template<int MODE>
__device__ __forceinline__ void gemm_body(const float* __restrict__ A,
                                          const float* __restrict__ W,
                                          float* __restrict__ out,
                                          const float* __restrict__ bias,
                                          float* sm, int bx, int by) {
    const int tid  = threadIdx.x;
    const int lane = tid & 31;
    const int wid  = tid >> 5;
    const int wm   = wid >> 1;
    const int wn   = wid & 1;

    float c[4][8][4];
#pragma unroll
    for (int i = 0; i < 4; i++)
#pragma unroll
        for (int j = 0; j < 8; j++)
#pragma unroll
            for (int k = 0; k < 4; k++) c[i][j][k] = 0.f;

    const int lr = tid >> 3;
    const int ls = tid & 7;
    const float* Ag = A + (size_t)(by * 128 + lr) * 1024 + ls * 4;
    const float* Wg = W + (size_t)(bx * 128 + lr) * 1024 + ls * 4;

    const uint32_t ldst = smem_u32(sm) + (lr * SROW + ls * 4) * 4;

    auto load_tile = [&](int kt, int s) {
        const uint32_t aB = ldst + (uint32_t)s * (STAGE_F * 4);
        const uint32_t bB = aB + STG_F * 4;
        const float* Ak = Ag + kt * 32;
        const float* Wk = Wg + kt * 32;
#pragma unroll
        for (int i = 0; i < 8; i++) {
            cp_async16(aB + i * 16 * (SROW * 4), Ak + (size_t)i * 16 * 1024);
            cp_async16(bB + i * 16 * (SROW * 4), Wk + (size_t)i * 16 * 1024);
        }
        asm volatile("cp.async.commit_group;" ::: "memory");
    };

    load_tile(0, 0);
    load_tile(1, 1);

    const int g = lane >> 2;
    const int q = lane & 3;

    uint32_t af[2][4][4], bf[2][8][2];   // double-buffered fragments

    auto frag_load = [&](const uint32_t* As, const uint32_t* Bs, int ks, int buf) {
        const int k0 = ks * 8 + q;
#pragma unroll
        for (int mm = 0; mm < 4; mm++) {
            af[buf][mm][0] = As[(mm * 16)     * SROW + k0];
            af[buf][mm][1] = As[(mm * 16 + 8) * SROW + k0];
            af[buf][mm][2] = As[(mm * 16)     * SROW + k0 + 4];
            af[buf][mm][3] = As[(mm * 16 + 8) * SROW + k0 + 4];
        }
#pragma unroll
        for (int nn = 0; nn < 8; nn++) {
            bf[buf][nn][0] = Bs[(nn * 8) * SROW + k0];
            bf[buf][nn][1] = Bs[(nn * 8) * SROW + k0 + 4];
        }
    };

    int s = 0, sl = 2;
    for (int kt = 0; kt < 32; kt++) {
        if (kt < 31) {
            asm volatile("cp.async.wait_group 1;" ::: "memory");
        } else {
            asm volatile("cp.async.wait_group 0;" ::: "memory");
        }
        __syncthreads();

        if (kt + 2 < 32) {
            load_tile(kt + 2, sl);
            sl = (sl == 2) ? 0 : sl + 1;
        }

        const uint32_t* As = (const uint32_t*)(sm + s * STAGE_F) +
                             (wm * 64 + g) * SROW;
        const uint32_t* Bs = (const uint32_t*)(sm + s * STAGE_F + STG_F) +
                             (wn * 64 + g) * SROW;

        frag_load(As, Bs, 0, 0);
#pragma unroll
        for (int ks = 0; ks < 4; ks++) {
            const int cur = ks & 1;
            if (ks < 3) frag_load(As, Bs, ks + 1, cur ^ 1);  // hide LDS under MMAs
#pragma unroll
            for (int mm = 0; mm < 4; mm++)
#pragma unroll
                for (int nn = 0; nn < 8; nn++)
                    mma_tf32(c[mm][nn], af[cur][mm], bf[cur][nn]);
        }
        s = (s == 2) ? 0 : s + 1;
    }

    const int rbase = by * 128 + wm * 64 + g;
    const int cbase = bx * 128 + wn * 64 + 2 * q;
#pragma unroll
    for (int mm = 0; mm < 4; mm++) {
        const int r0 = rbase + mm * 16;
#pragma unroll
        for (int nn = 0; nn < 8; nn++) {
            const int cc = cbase + nn * 8;
            if (MODE == 0) {
                const int h = cc >> 6, d = cc & 63;
                const int b = r0 >> 11, t = r0 & 2047;
                float* dst = out + (((size_t)(b * H_ + h)) * T_ + t) * HD_ + d;
                *(float2*)dst =
                    make_float2(rna_tf32(c[mm][nn][0]), rna_tf32(c[mm][nn][1]));
                *(float2*)(dst + 8 * HD_) =
                    make_float2(rna_tf32(c[mm][nn][2]), rna_tf32(c[mm][nn][3]));
            } else {
                float2 bb = *(const float2*)(bias + cc);
                float* dst = out + (size_t)r0 * 1024 + cc;
                *(float2*)dst = make_float2(c[mm][nn][0] + bb.x, c[mm][nn][1] + bb.y);
                *(float2*)(dst + 8 * 1024) =
                    make_float2(c[mm][nn][2] + bb.x, c[mm][nn][3] + bb.y);
            }
        }
    }
}

// Fused QKV: grid (8, 64, 3); z selects which projection.
__global__ void __launch_bounds__(128) gemm_qkv(const float* __restrict__ A,
                                                const float* __restrict__ Wr,
                                                float* __restrict__ o0,
                                                float* __restrict__ o1,
                                                float* __restrict__ o2) {
    extern __shared__ float sm[];
    const int z = blockIdx.z;
    const float* W = Wr + (size_t)z * D_ * D_;
    float* out = (z == 0) ? o0 : (z == 1) ? o1 : o2;
    gemm_body<0>(A, W, out, nullptr, sm, blockIdx.x, blockIdx.y);
}

__global__ void __launch_bounds__(128) gemm_out(const float* __restrict__ A,
                                                const float* __restrict__ W,
                                                float* __restrict__ out,
                                                const float* __restrict__ bias) {
    extern __shared__ float sm[];
    gemm_body<1>(A, W, out, bias, sm, blockIdx.x, blockIdx.y);
}

// ---------------------------------------------------------------------------
// Tensor-core flash attention (causal), tf32 mma.sync. (unchanged, known good)
// ---------------------------------------------------------------------------
#define PADK 68
#define KS_F (64 * PADK)

__global__ void __launch_bounds__(256) flash_mma() {
    extern __shared__ float sm[];
    float* Ks = sm;
    float* Vt = sm + 2 * KS_F;
    float* Ps = sm + 3 * KS_F;

    const int tid = threadIdx.x, lane = tid & 31, wid = tid >> 5;
    const int g = lane >> 2, q = lane & 3;
    const int qt = blockIdx.x, bh = blockIdx.y;
    const int w16 = wid * 16;

    const float* Qg = g_q + (size_t)bh * T_ * HD_ + (size_t)qt * 128 * HD_;
    const float* Kg = g_k + (size_t)bh * T_ * HD_;
    const float* Vg = g_v + (size_t)bh * T_ * HD_;

    const uint32_t sb  = smem_u32(sm);
    const uint32_t VtB = sb + 2 * KS_F * 4;
    const uint32_t PsB = VtB + KS_F * 4;

    {
        const int row = tid >> 1, segb = (tid & 1) * 8;
#pragma unroll
        for (int i = 0; i < 8; i++)
            cp_async16(PsB + (row * PADK + (segb + i) * 4) * 4,
                       Qg + row * 64 + (segb + i) * 4);
    }
#pragma unroll
    for (int i = 0; i < 4; i++) {
        const int idx = tid + i * 256;
        cp_async16(sb + ((idx >> 4) * PADK + (idx & 15) * 4) * 4,
                   Kg + (idx >> 4) * 64 + (idx & 15) * 4);
    }
    asm volatile("cp.async.commit_group;" ::: "memory");

    const int vr = tid & 63, vqr = tid >> 6;
    float4 vreg[4];
#pragma unroll
    for (int i = 0; i < 4; i++)
        vreg[i] = *(const float4*)(Vg + vr * 64 + vqr * 16 + i * 4);

    asm volatile("cp.async.wait_group 0;" ::: "memory");
    __syncthreads();

    uint32_t qf[8][4];
#pragma unroll
    for (int ks = 0; ks < 8; ks++) {
        qf[ks][0] = __float_as_uint(Ps[(w16 + g) * PADK + ks * 8 + q] * 0.125f);
        qf[ks][1] = __float_as_uint(Ps[(w16 + g + 8) * PADK + ks * 8 + q] * 0.125f);
        qf[ks][2] = __float_as_uint(Ps[(w16 + g) * PADK + ks * 8 + q + 4] * 0.125f);
        qf[ks][3] = __float_as_uint(Ps[(w16 + g + 8) * PADK + ks * 8 + q + 4] * 0.125f);
    }
    __syncthreads();

#pragma unroll
    for (int i = 0; i < 4; i++) {
        Vt[(vqr * 16 + i * 4 + 0) * PADK + vr] = vreg[i].x;
        Vt[(vqr * 16 + i * 4 + 1) * PADK + vr] = vreg[i].y;
        Vt[(vqr * 16 + i * 4 + 2) * PADK + vr] = vreg[i].z;
        Vt[(vqr * 16 + i * 4 + 3) * PADK + vr] = vreg[i].w;
    }
    __syncthreads();

    float o_[8][4];
#pragma unroll
    for (int j = 0; j < 8; j++)
#pragma unroll
        for (int k = 0; k < 4; k++) o_[j][k] = 0.f;
    float m0 = -1e30f, m1 = -1e30f, l0 = 0.f, l1 = 0.f;

    const int nkt = 2 * qt + 2;
    for (int kt = 0; kt < nkt; kt++) {
        const int s = kt & 1;

        if (kt + 1 < nkt) {
            const float* Kn = Kg + (size_t)(kt + 1) * 64 * 64;
#pragma unroll
            for (int i = 0; i < 4; i++) {
                const int idx = tid + i * 256;
                cp_async16(sb + ((s ^ 1) * KS_F + (idx >> 4) * PADK + (idx & 15) * 4) * 4,
                           Kn + (idx >> 4) * 64 + (idx & 15) * 4);
            }
            asm volatile("cp.async.commit_group;" ::: "memory");
            const float* Vn = Vg + (size_t)(kt + 1) * 64 * 64;
#pragma unroll
            for (int i = 0; i < 4; i++)
                vreg[i] = *(const float4*)(Vn + vr * 64 + vqr * 16 + i * 4);
        }

        float s_[8][4];
#pragma unroll
        for (int j = 0; j < 8; j++)
#pragma unroll
            for (int k = 0; k < 4; k++) s_[j][k] = 0.f;

        const float* Kb = Ks + s * KS_F;
#pragma unroll
        for (int ks = 0; ks < 8; ks++) {
#pragma unroll
            for (int j = 0; j < 8; j++) {
                const uint32_t b0 = __float_as_uint(Kb[(j * 8 + g) * PADK + ks * 8 + q]);
                const uint32_t b1 = __float_as_uint(Kb[(j * 8 + g) * PADK + ks * 8 + q + 4]);
                mma_tf32_b(s_[j], qf[ks], b0, b1);
            }
        }

        if (kt >= 2 * qt) {
            const int kb = kt * 64;
            const int r0 = qt * 128 + w16 + g, r1 = r0 + 8;
#pragma unroll
            for (int j = 0; j < 8; j++) {
                const int k0 = kb + j * 8 + 2 * q;
                if (k0 > r0)     s_[j][0] = -1e30f;
                if (k0 + 1 > r0) s_[j][1] = -1e30f;
                if (k0 > r1)     s_[j][2] = -1e30f;
                if (k0 + 1 > r1) s_[j][3] = -1e30f;
            }
        }

        float mx0 = -1e30f, mx1 = -1e30f;
#pragma unroll
        for (int j = 0; j < 8; j++) {
            mx0 = fmaxf(mx0, fmaxf(s_[j][0], s_[j][1]));
            mx1 = fmaxf(mx1, fmaxf(s_[j][2], s_[j][3]));
        }
        mx0 = fmaxf(mx0, __shfl_xor_sync(0xffffffffu, mx0, 1));
        mx0 = fmaxf(mx0, __shfl_xor_sync(0xffffffffu, mx0, 2));
        mx1 = fmaxf(mx1, __shfl_xor_sync(0xffffffffu, mx1, 1));
        mx1 = fmaxf(mx1, __shfl_xor_sync(0xffffffffu, mx1, 2));

        const float mn0 = fmaxf(m0, mx0), mn1 = fmaxf(m1, mx1);
        const float ex0 = __expf(m0 - mn0), ex1 = __expf(m1 - mn1);
        float rs0 = 0.f, rs1 = 0.f;
#pragma unroll
        for (int j = 0; j < 8; j++) {
            s_[j][0] = rna_tf32(__expf(s_[j][0] - mn0));
            s_[j][1] = rna_tf32(__expf(s_[j][1] - mn0));
            s_[j][2] = rna_tf32(__expf(s_[j][2] - mn1));
            s_[j][3] = rna_tf32(__expf(s_[j][3] - mn1));
            rs0 += s_[j][0] + s_[j][1];
            rs1 += s_[j][2] + s_[j][3];
        }
        rs0 += __shfl_xor_sync(0xffffffffu, rs0, 1);
        rs0 += __shfl_xor_sync(0xffffffffu, rs0, 2);
        rs1 += __shfl_xor_sync(0xffffffffu, rs1, 1);
        rs1 += __shfl_xor_sync(0xffffffffu, rs1, 2);
        l0 = l0 * ex0 + rs0;  m0 = mn0;
        l1 = l1 * ex1 + rs1;  m1 = mn1;
#pragma unroll
        for (int j = 0; j < 8; j++) {
            o_[j][0] *= ex0; o_[j][1] *= ex0;
            o_[j][2] *= ex1; o_[j][3] *= ex1;
        }

#pragma unroll
        for (int j = 0; j < 8; j++) {
            *(float2*)&Ps[(w16 + g) * PADK + j * 8 + 2 * q] =
                make_float2(s_[j][0], s_[j][1]);
            *(float2*)&Ps[(w16 + g + 8) * PADK + j * 8 + 2 * q] =
                make_float2(s_[j][2], s_[j][3]);
        }
        __syncwarp();

#pragma unroll
        for (int ks = 0; ks < 8; ks++) {
            uint32_t a[4];
            a[0] = __float_as_uint(Ps[(w16 + g) * PADK + ks * 8 + q]);
            a[1] = __float_as_uint(Ps[(w16 + g + 8) * PADK + ks * 8 + q]);
            a[2] = __float_as_uint(Ps[(w16 + g) * PADK + ks * 8 + q + 4]);
            a[3] = __float_as_uint(Ps[(w16 + g + 8) * PADK + ks * 8 + q + 4]);
#pragma unroll
            for (int j = 0; j < 8; j++) {
                const uint32_t b0 = __float_as_uint(Vt[(j * 8 + g) * PADK + ks * 8 + q]);
                const uint32_t b1 = __float_as_uint(Vt[(j * 8 + g) * PADK + ks * 8 + q + 4]);
                mma_tf32_b(o_[j], a, b0, b1);
            }
        }

        if (kt + 1 < nkt) {
            __syncthreads();
#pragma unroll
            for (int i = 0; i < 4; i++) {
                Vt[(vqr * 16 + i * 4 + 0) * PADK + vr] = vreg[i].x;
                Vt[(vqr * 16 + i * 4 + 1) * PADK + vr] = vreg[i].y;
                Vt[(vqr * 16 + i * 4 + 2) * PADK + vr] = vreg[i].z;
                Vt[(vqr * 16 + i * 4 + 3) * PADK + vr] = vreg[i].w;
            }
            asm volatile("cp.async.wait_group 0;" ::: "memory");
            __syncthreads();
        }
    }

    const int b = bh >> 4, h = bh & 15;
    const float inv0 = 1.f / l0, inv1 = 1.f / l1;
    const int t0 = qt * 128 + w16 + g;
    float* dst0 = g_o + ((size_t)(b * T_ + t0)) * D_ + h * 64;
    float* dst1 = g_o + ((size_t)(b * T_ + t0 + 8)) * D_ + h * 64;
#pragma unroll
    for (int j = 0; j < 8; j++) {
        *(float2*)(dst0 + j * 8 + 2 * q) =
            make_float2(rna_tf32(o_[j][0] * inv0), rna_tf32(o_[j][1] * inv0));
        *(float2*)(dst1 + j * 8 + 2 * q) =
            make_float2(rna_tf32(o_[j][2] * inv1), rna_tf32(o_[j][3] * inv1));
    }
}

// ---------------------------------------------------------------------------
// Launch
// ---------------------------------------------------------------------------
extern "C" void kernel_launch(void* const* d_in, const int* in_sizes, int n_in,
                              void* d_out, int out_size) {
    const float* x  = (const float*)d_in[0];
    const float* Wk = (const float*)d_in[1];
    const float* Wq = (const float*)d_in[2];
    const float* Wv = (const float*)d_in[3];
    const float* Wp = (const float*)d_in[4];
    const float* bp = (const float*)d_in[5];
    float* out = (float*)d_out;

    float *qp, *kp, *vp, *op, *xr, *wr;
    cudaGetSymbolAddress((void**)&qp, g_q);
    cudaGetSymbolAddress((void**)&kp, g_k);
    cudaGetSymbolAddress((void**)&vp, g_v);
    cudaGetSymbolAddress((void**)&op, g_o);
    cudaGetSymbolAddress((void**)&xr, g_xr);
    cudaGetSymbolAddress((void**)&wr, g_wr);

    cudaFuncSetAttribute(gemm_qkv, cudaFuncAttributeMaxDynamicSharedMemorySize, GSMEM);
    cudaFuncSetAttribute(gemm_out, cudaFuncAttributeMaxDynamicSharedMemorySize, GSMEM);

    const int NX = B_ * T_ * D_;
    const int NW = D_ * D_;

    // rounding: x + all 4 weights (2 launches)
    round_tf32<<<NX / 1024, 256>>>(x, xr);
    WPtrs ws; ws.w[0] = Wk; ws.w[1] = Wq; ws.w[2] = Wv; ws.w[3] = Wp;
    round_w4<<<dim3(NW / 1024, 4), 256>>>(ws, wr);

    // fused QKV projections
    gemm_qkv<<<dim3(D_ / 128, M_ / 128, 3), 128, GSMEM>>>(xr, wr, kp, qp, vp);

    // tensor-core flash attention
    const int fl_smem = (2 * KS_F + KS_F + 128 * PADK) * sizeof(float);  // 87040
    cudaFuncSetAttribute(flash_mma, cudaFuncAttributeMaxDynamicSharedMemorySize, fl_smem);
    flash_mma<<<dim3(T_ / 128, B_ * H_), 256, fl_smem>>>();

    // output projection
    gemm_out<<<dim3(D_ / 128, M_ / 128), 128, GSMEM>>>(op, wr + 3 * (size_t)NW, out, bp);
}